// round 13
// baseline (speedup 1.0000x reference)
#include <cuda_runtime.h>
#include <cuda_bf16.h>
#include <math.h>

#define BB   2
#define SS   2048
#define DD   1024
#define HH   16
#define HDIM 64
#define DFFN 2048
#define BH   (BB*HH)

// ---------------- scratch (static __device__, no allocations) ----------------
__device__ float g_xh [BH*SS*HDIM];
__device__ float g_q  [BH*SS*HDIM];
__device__ float g_k  [BH*SS*HDIM];
__device__ float g_kT [BH*HDIM*SS];
__device__ float g_A  [(size_t)BH*SS*SS];                 // fp32 scores (512 MB)
// A and state bf16 splits live in CHUNK-TILED + SWIZZLED layout (see aidx/sidx)
__device__ __nv_bfloat16 g_Ahi[(size_t)BH*SS*SS];
__device__ __nv_bfloat16 g_Alo[(size_t)BH*SS*SS];
__device__ float         g_st  [(size_t)BH*128*SS];       // linear [bh][n][k]
__device__ __nv_bfloat16 g_sthi[(size_t)BH*128*SS];
__device__ __nv_bfloat16 g_stlo[(size_t)BH*128*SS];
__device__ float         g_apf [(size_t)BH*128*SS];
__device__ __nv_bfloat16 g_aphi[(size_t)BH*128*SS];
__device__ __nv_bfloat16 g_aplo[(size_t)BH*128*SS];
__device__ float         g_d1  [(size_t)BH*128*SS];
__device__ float g_attnv[(size_t)BH*64*SS];
__device__ float g_mixed[(size_t)BH*64*SS];
__device__ float g_x1 [BB*SS*DD];
__device__ float g_xn2[BB*SS*DD];
__device__ float g_hb [(size_t)BB*SS*DFFN];

// ---------------- tiled+swizzled index helpers ----------------
__device__ __forceinline__ size_t aidx(int bh, int m, int k) {
    return ((((size_t)bh * 32 + (k >> 6)) * 2048 + m) * 8 + ((((k >> 3) & 7) ^ (m & 7)))) * 8
           + (k & 7);
}
__device__ __forceinline__ size_t sidx(int bh, int n, int k) {
    return ((((size_t)bh * 32 + (k >> 6)) * 128 + n) * 8 + ((((k >> 3) & 7) ^ (n & 7)))) * 8
           + (k & 7);
}

// ---------------- generic helpers ----------------
__device__ __forceinline__ unsigned long long pk2(float lo, float hi) {
    unsigned long long r;
    asm("mov.b64 %0, {%1,%2};" : "=l"(r) : "f"(lo), "f"(hi));
    return r;
}
__device__ __forceinline__ unsigned long long f2fma(unsigned long long a,
                                                    unsigned long long b,
                                                    unsigned long long c) {
    unsigned long long d;
    asm("fma.rn.f32x2 %0, %1, %2, %3;" : "=l"(d) : "l"(a), "l"(b), "l"(c));
    return d;
}
__device__ __forceinline__ float2 upk(unsigned long long v) {
    float2 f;
    asm("mov.b64 {%0,%1}, %2;" : "=f"(f.x), "=f"(f.y) : "l"(v));
    return f;
}
__device__ __forceinline__ float gelu_tanh(float x) {
    float x3 = x * x * x;
    return 0.5f * x * (1.0f + tanhf(0.7978845608028654f * (x + 0.044715f * x3)));
}
__device__ __forceinline__ float blockReduceSum(float v, float* sdata) {
    int tid = threadIdx.x;
    sdata[tid] = v; __syncthreads();
    for (int s = 128; s > 0; s >>= 1) {
        if (tid < s) sdata[tid] += sdata[tid + s];
        __syncthreads();
    }
    float r = sdata[0]; __syncthreads();
    return r;
}
__device__ __forceinline__ float blockReduceMax(float v, float* sdata) {
    int tid = threadIdx.x;
    sdata[tid] = v; __syncthreads();
    for (int s = 128; s > 0; s >>= 1) {
        if (tid < s) sdata[tid] = fmaxf(sdata[tid], sdata[tid + s]);
        __syncthreads();
    }
    float r = sdata[0]; __syncthreads();
    return r;
}
__device__ __forceinline__ void split_bf16(float v, __nv_bfloat16& hi, __nv_bfloat16& lo) {
    hi = __float2bfloat16(v);
    lo = __float2bfloat16(v - __bfloat162float(hi));
}
__device__ __forceinline__ unsigned int s2u(const void* p) {
    unsigned int a;
    asm("{ .reg .u64 t; cvta.to.shared.u64 t, %1; cvt.u32.u64 %0, t; }" : "=r"(a) : "l"(p));
    return a;
}

// ---------------- warp-mma + async-bulk helpers ----------------
__device__ __forceinline__ void ldmx4(unsigned int* r, unsigned int addr) {
    asm volatile("ldmatrix.sync.aligned.m8n8.x4.shared.b16 {%0,%1,%2,%3}, [%4];"
                 : "=r"(r[0]), "=r"(r[1]), "=r"(r[2]), "=r"(r[3]) : "r"(addr));
}
__device__ __forceinline__ void mma16816(float* c, const unsigned int* a,
                                         const unsigned int b0, const unsigned int b1) {
    asm volatile(
        "mma.sync.aligned.m16n8k16.row.col.f32.bf16.bf16.f32 "
        "{%0,%1,%2,%3}, {%4,%5,%6,%7}, {%8,%9}, {%0,%1,%2,%3};"
        : "+f"(c[0]), "+f"(c[1]), "+f"(c[2]), "+f"(c[3])
        : "r"(a[0]), "r"(a[1]), "r"(a[2]), "r"(a[3]), "r"(b0), "r"(b1));
}
__device__ __forceinline__ void bulk_cp(unsigned int dst, const void* src,
                                        unsigned int bytes, unsigned int mbar) {
    asm volatile(
        "cp.async.bulk.shared::cta.global.mbarrier::complete_tx::bytes [%0], [%1], %2, [%3];"
        :: "r"(dst), "l"(src), "r"(bytes), "r"(mbar) : "memory");
}
__device__ __forceinline__ void mbar_init(unsigned int mbar, unsigned int cnt) {
    asm volatile("mbarrier.init.shared.b64 [%0], %1;" :: "r"(mbar), "r"(cnt) : "memory");
}
__device__ __forceinline__ void mbar_expect(unsigned int mbar, unsigned int bytes) {
    asm volatile("mbarrier.arrive.expect_tx.shared.b64 _, [%0], %1;"
                 :: "r"(mbar), "r"(bytes) : "memory");
}
__device__ __forceinline__ void mbar_wait(unsigned int mbar, unsigned int parity) {
    asm volatile(
        "{\n\t"
        ".reg .pred P1;\n\t"
        "LAB_WAIT_%=:\n\t"
        "mbarrier.try_wait.parity.acquire.cta.shared::cta.b64 P1, [%0], %1, 0x989680;\n\t"
        "@P1 bra.uni DONE_%=;\n\t"
        "bra.uni LAB_WAIT_%=;\n\t"
        "DONE_%=:\n\t"
        "}"
        :: "r"(mbar), "r"(parity) : "memory");
}

// ---------------- LayerNorm ----------------
__global__ void ln_kernel(const float* __restrict__ x, const float* __restrict__ g,
                          const float* __restrict__ be, float* __restrict__ out, int mode) {
    __shared__ float sred[256];
    int row = blockIdx.x;
    int tid = threadIdx.x;
    const float* xr = x + (size_t)row * DD;
    float v[4];
    float s = 0.f;
#pragma unroll
    for (int kk = 0; kk < 4; kk++) { v[kk] = xr[tid + 256 * kk]; s += v[kk]; }
    s = blockReduceSum(s, sred);
    float mean = s * (1.0f / DD);
    float qv = 0.f;
#pragma unroll
    for (int kk = 0; kk < 4; kk++) { float d = v[kk] - mean; qv += d * d; }
    qv = blockReduceSum(qv, sred);
    float inv = rsqrtf(qv * (1.0f / DD) + 1e-5f);
    int b = row / SS, sidx_ = row % SS;
#pragma unroll
    for (int kk = 0; kk < 4; kk++) {
        int j = tid + 256 * kk;
        float y = (v[kk] - mean) * inv * g[j] + be[j];
        if (mode == 0) {
            int h = j >> 6, d = j & 63;
            out[(((size_t)(b * HH + h)) * SS + sidx_) * HDIM + d] = y;
        } else {
            out[(size_t)row * DD + j] = y;
        }
    }
}

// ---------------- QKV projection ----------------
__global__ void qkv_kernel(const float* __restrict__ xh, const float* __restrict__ Wq,
                           const float* __restrict__ Wk, const float* __restrict__ Wv,
                           float* __restrict__ qo, float* __restrict__ ko,
                           float* __restrict__ stf, __nv_bfloat16* __restrict__ sthi,
                           __nv_bfloat16* __restrict__ stlo) {
    __shared__ float Xs[64][65];
    __shared__ float Ws[64][65];
    int s0 = blockIdx.x * 64;
    int bh = blockIdx.y;
    int h = bh % HH;
    int tid = threadIdx.x, tx = tid % 16, ty = tid / 16;
    const float* xb = xh + ((size_t)bh * SS + s0) * HDIM;
    for (int t = tid; t < 1024; t += 256) {
        int r = t / 16, c4 = t % 16;
        float4 vv = *(const float4*)(xb + r * 64 + c4 * 4);
        Xs[r][c4 * 4 + 0] = vv.x; Xs[r][c4 * 4 + 1] = vv.y;
        Xs[r][c4 * 4 + 2] = vv.z; Xs[r][c4 * 4 + 3] = vv.w;
    }
    const float* Wm[3] = { Wq + h * 4096, Wk + h * 4096, Wv + h * 4096 };
    for (int m = 0; m < 3; m++) {
        __syncthreads();
        for (int t = tid; t < 1024; t += 256) {
            int r = t / 16, c4 = t % 16;
            float4 vv = *(const float4*)(Wm[m] + r * 64 + c4 * 4);
            Ws[r][c4 * 4 + 0] = vv.x; Ws[r][c4 * 4 + 1] = vv.y;
            Ws[r][c4 * 4 + 2] = vv.z; Ws[r][c4 * 4 + 3] = vv.w;
        }
        __syncthreads();
        float acc[4][4] = {};
#pragma unroll 8
        for (int kk = 0; kk < 64; kk++) {
            float xv[4], wv[4];
#pragma unroll
            for (int i = 0; i < 4; i++) xv[i] = Xs[ty * 4 + i][kk];
#pragma unroll
            for (int j = 0; j < 4; j++) wv[j] = Ws[kk][tx * 4 + j];
#pragma unroll
            for (int i = 0; i < 4; i++)
#pragma unroll
                for (int j = 0; j < 4; j++) acc[i][j] += xv[i] * wv[j];
        }
#pragma unroll
        for (int i = 0; i < 4; i++) {
            int srow = s0 + ty * 4 + i;
            size_t base = (size_t)bh * SS + srow;
#pragma unroll
            for (int j = 0; j < 4; j++) {
                int c = tx * 4 + j;
                if (m == 0)      qo[base * HDIM + c] = acc[i][j];
                else if (m == 1) ko[base * HDIM + c] = acc[i][j];
                else {
                    float v = acc[i][j];
                    __nv_bfloat16 hi, lo; split_bf16(v, hi, lo);
                    size_t lb = ((size_t)bh << 18) + ((size_t)c << 11) + srow;
                    stf[lb] = v; stf[lb + 131072] = 0.f;
                    size_t th = sidx(bh, c, srow), tb = sidx(bh, c + 64, srow);
                    sthi[th] = hi; stlo[th] = lo;
                    sthi[tb] = __float2bfloat16(0.f);
                    stlo[tb] = __float2bfloat16(0.f);
                }
            }
        }
    }
}

// ---------------- k transpose ----------------
__global__ void transpose_k(const float* __restrict__ k, float* __restrict__ kT) {
    __shared__ float t[32][33];
    int s0 = blockIdx.x * 32, d0 = blockIdx.y * 32, bh = blockIdx.z;
    const float* kb = k + (size_t)bh * SS * HDIM;
    float* kTb = kT + (size_t)bh * HDIM * SS;
    for (int r = threadIdx.y; r < 32; r += 8)
        t[r][threadIdx.x] = kb[(size_t)(s0 + r) * HDIM + d0 + threadIdx.x];
    __syncthreads();
    for (int r = threadIdx.y; r < 32; r += 8)
        kTb[(size_t)(d0 + r) * SS + s0 + threadIdx.x] = t[threadIdx.x][r];
}

// ---------------- row softmax -> bf16 hi/lo in tiled layout ----------------
__global__ void softmax_kernel(const float* __restrict__ A,
                               __nv_bfloat16* __restrict__ Ahi,
                               __nv_bfloat16* __restrict__ Alo) {
    __shared__ float sred[256];
    size_t rb = (size_t)blockIdx.x * SS;
    const float* ar = A + rb;
    int bh = blockIdx.x >> 11, m = blockIdx.x & 2047;
    int tid = threadIdx.x;
    float r[8];
    float mx = -1e30f;
#pragma unroll
    for (int kk = 0; kk < 8; kk++) { r[kk] = ar[tid + 256 * kk]; mx = fmaxf(mx, r[kk]); }
    mx = blockReduceMax(mx, sred);
    float s = 0.f;
#pragma unroll
    for (int kk = 0; kk < 8; kk++) { r[kk] = __expf(r[kk] - mx); s += r[kk]; }
    s = blockReduceSum(s, sred);
    float inv = 1.0f / s;
#pragma unroll
    for (int kk = 0; kk < 8; kk++) {
        float val = r[kk] * inv;
        __nv_bfloat16 hi, lo; split_bf16(val, hi, lo);
        size_t ai = aidx(bh, m, tid + 256 * kk);
        Ahi[ai] = hi;
        Alo[ai] = lo;
    }
}

// ---------------- fused HMMA A-apply + ODE eval (3-stage bulk pipeline) ----------------
// mode 0: eval1; 1: eval1+capture attnv; 2: eval2
#define CA 0.99500416527802576610f
#define SA 0.09983341664682815230f
#define STAGE_B 65536
#define SMEM_BULK (128 + 3 * STAGE_B)   // 196736
__global__ void __launch_bounds__(256) apply_fused(
    const __nv_bfloat16* __restrict__ Ahi, const __nv_bfloat16* __restrict__ Alo,
    const __nv_bfloat16* __restrict__ Bhi, const __nv_bfloat16* __restrict__ Blo,
    float* __restrict__ st, float* __restrict__ apf, float* __restrict__ d1,
    const float* __restrict__ omega,
    __nv_bfloat16* __restrict__ out_hi, __nv_bfloat16* __restrict__ out_lo,
    float* __restrict__ attnv, int mode)
{
    extern __shared__ char smem[];
    unsigned int sb = s2u(smem);
    int tid = threadIdx.x, wid = tid >> 5, lane = tid & 31;
    int m0 = blockIdx.x << 7;
    int bh = blockIdx.y;
    int wm = (wid >> 2) * 64, wn = (wid & 3) * 32;

    unsigned int mb[3] = { sb, sb + 8, sb + 16 };
    if (tid == 0) { mbar_init(mb[0], 1); mbar_init(mb[1], 1); mbar_init(mb[2], 1); }
    __syncthreads();

    const char* pAh = (const char*)Ahi;
    const char* pAl = (const char*)Alo;
    const char* pBh = (const char*)Bhi;
    const char* pBl = (const char*)Blo;

    float c[4][4][4];
#pragma unroll
    for (int i = 0; i < 4; i++)
#pragma unroll
        for (int j = 0; j < 4; j++)
#pragma unroll
            for (int r = 0; r < 4; r++) c[i][j][r] = 0.f;

    int arow = ((lane >> 3) & 1) * 8 + (lane & 7);
    int brow = (lane >> 4) * 8 + (lane & 7);
    int ua = (lane >> 4);
    int ub = ((lane >> 3) & 1);
    int rx = lane & 7;
    unsigned int aRow = (wm + arow) * 128;
    unsigned int bRow = (wn + brow) * 128;

    // prologue: issue chunks 0,1,2 into stages 0,1,2
    if (tid == 0) {
#pragma unroll
        for (int p = 0; p < 3; p++) {
            mbar_expect(mb[p], 4 * 16384);
            unsigned int dst = sb + 128 + p * STAGE_B;
            size_t aoff = (((size_t)bh * 32 + p) * 2048 + m0) * 128;
            size_t boff = (((size_t)bh * 32 + p) * 128) * 128;
            bulk_cp(dst,          pAh + aoff, 16384, mb[p]);
            bulk_cp(dst + 16384,  pAl + aoff, 16384, mb[p]);
            bulk_cp(dst + 32768,  pBh + boff, 16384, mb[p]);
            bulk_cp(dst + 49152,  pBl + boff, 16384, mb[p]);
        }
    }

    for (int ck = 0; ck < 32; ck++) {
        int s = ck % 3;
        mbar_wait(mb[s], (ck / 3) & 1);

        unsigned int base = sb + 128 + s * STAGE_B;
#pragma unroll
        for (int ks = 0; ks < 4; ks++) {
            unsigned int au = (unsigned int)(((ua + 2 * ks) ^ rx) << 4);
            unsigned int bu = (unsigned int)(((ub + 2 * ks) ^ rx) << 4);
            unsigned int a[4][4];
            unsigned int b[2][4];
            // --- Ah x Bh ---
#pragma unroll
            for (int ma = 0; ma < 4; ma++) ldmx4(a[ma], base + aRow + ma * 2048 + au);
#pragma unroll
            for (int p = 0; p < 2; p++) ldmx4(b[p], base + 32768 + bRow + p * 2048 + bu);
#pragma unroll
            for (int ma = 0; ma < 4; ma++)
#pragma unroll
                for (int na = 0; na < 4; na++)
                    mma16816(c[ma][na], a[ma], b[na >> 1][(na & 1) * 2],
                             b[na >> 1][(na & 1) * 2 + 1]);
            // --- Al x Bh ---
#pragma unroll
            for (int ma = 0; ma < 4; ma++)
                ldmx4(a[ma], base + 16384 + aRow + ma * 2048 + au);
#pragma unroll
            for (int ma = 0; ma < 4; ma++)
#pragma unroll
                for (int na = 0; na < 4; na++)
                    mma16816(c[ma][na], a[ma], b[na >> 1][(na & 1) * 2],
                             b[na >> 1][(na & 1) * 2 + 1]);
            // --- Ah x Bl ---
#pragma unroll
            for (int ma = 0; ma < 4; ma++) ldmx4(a[ma], base + aRow + ma * 2048 + au);
#pragma unroll
            for (int p = 0; p < 2; p++)
                ldmx4(b[p], base + 49152 + bRow + p * 2048 + bu);
#pragma unroll
            for (int ma = 0; ma < 4; ma++)
#pragma unroll
                for (int na = 0; na < 4; na++)
                    mma16816(c[ma][na], a[ma], b[na >> 1][(na & 1) * 2],
                             b[na >> 1][(na & 1) * 2 + 1]);
        }
        __syncthreads();
        if (tid == 0 && ck + 3 < 32) {
            mbar_expect(mb[s], 4 * 16384);
            unsigned int dst = sb + 128 + s * STAGE_B;
            size_t aoff = (((size_t)bh * 32 + (ck + 3)) * 2048 + m0) * 128;
            size_t boff = (((size_t)bh * 32 + (ck + 3)) * 128) * 128;
            bulk_cp(dst,          pAh + aoff, 16384, mb[s]);
            bulk_cp(dst + 16384,  pAl + aoff, 16384, mb[s]);
            bulk_cp(dst + 32768,  pBh + boff, 16384, mb[s]);
            bulk_cp(dst + 49152,  pBl + boff, 16384, mb[s]);
        }
    }

    // stage z into smem (reuse stage buffers), 129-float row stride
    float* zs = (float*)(smem + 128);
    int g = lane >> 2, tg = lane & 3;
#pragma unroll
    for (int ma = 0; ma < 4; ma++) {
        int ml = wm + ma * 16 + g;
#pragma unroll
        for (int na = 0; na < 4; na++) {
            int nl = wn + na * 8 + tg * 2;
            zs[nl * 129 + ml]           = c[ma][na][0];
            zs[(nl + 1) * 129 + ml]     = c[ma][na][1];
            zs[nl * 129 + ml + 8]       = c[ma][na][2];
            zs[(nl + 1) * 129 + ml + 8] = c[ma][na][3];
        }
    }
    __syncthreads();

    // fused ODE eval over (d in [0,64), k = m0 + kl)
    int hbase = (bh & (HH - 1)) << 6;
    for (int it = 0; it < 32; it++) {
        int idx = tid + (it << 8);          // 0..8191
        int kl = idx & 127;
        int d = idx >> 7;
        int k = m0 + kl;
        size_t lbase = ((size_t)bh << 18) + ((size_t)d << 11) + k;
        size_t lbb = lbase + 131072;
        float za = zs[d * 129 + kl];
        float zb = zs[(d + 64) * 129 + kl];
        float om = omega[hbase + d];
        float ra = za * CA + zb * SA;
        float rb = zb * CA - za * SA;
        __nv_bfloat16 hi, lo;
        size_t th = sidx(bh, d, k), tb2 = sidx(bh, d + 64, k);
        if (mode != 2) {
            float a = st[lbase], b = st[lbb];
            float r2 = a * a + b * b;
            float da = (1.0f - r2) * a - om * b + 3.0f * (ra - a);
            float db = (1.0f - r2) * b + om * a + 3.0f * (rb - b);
            d1[lbase] = da; d1[lbb] = db;
            float apv = a + 0.02f * da, bpv = b + 0.02f * db;
            apf[lbase] = apv; apf[lbb] = bpv;
            split_bf16(apv, hi, lo); out_hi[th] = hi; out_lo[th] = lo;
            split_bf16(bpv, hi, lo); out_hi[tb2] = hi; out_lo[tb2] = lo;
            if (mode == 1) attnv[((size_t)bh << 17) + ((size_t)d << 11) + k] = za;
        } else {
            float a = st[lbase], b = st[lbb];
            float ap = apf[lbase], bp = apf[lbb];
            float da1 = d1[lbase], db1 = d1[lbb];
            float r2 = ap * ap + bp * bp;
            float da2 = (1.0f - r2) * ap - om * bp + 3.0f * (ra - ap);
            float db2 = (1.0f - r2) * bp + om * ap + 3.0f * (rb - bp);
            float na = a + 0.01f * (da1 + da2);
            float nb = b + 0.01f * (db1 + db2);
            st[lbase] = na; st[lbb] = nb;
            split_bf16(na, hi, lo); out_hi[th] = hi; out_lo[th] = lo;
            split_bf16(nb, hi, lo); out_hi[tb2] = hi; out_lo[tb2] = lo;
        }
    }
}

// ---------------- fp32x2 GEMM (scores + MLP) ----------------
__global__ void __launch_bounds__(256, 2) gemm128(
    const float* __restrict__ A, const float* __restrict__ Bm, float* __restrict__ C,
    int M, int N, int K, int lda, int ldb, int ldc,
    size_t sA, size_t sB, size_t sC,
    int epi, const float* __restrict__ bias, const float* __restrict__ resid, float scale) {
    A  += (size_t)blockIdx.z * sA;
    Bm += (size_t)blockIdx.z * sB;
    C  += (size_t)blockIdx.z * sC;
    __shared__ float Ast[32][132];
    __shared__ float Xs[32][128];
    int m0 = blockIdx.x * 128, n0 = blockIdx.y * 128;
    int tid = threadIdx.x, tx = tid % 16, ty = tid / 16;
    int r0 = ty * 8, c0 = tx * 8;
    unsigned long long acc[8][4] = {};

    for (int kt = 0; kt < K; kt += 32) {
#pragma unroll
        for (int t = 0; t < 4; t++) {
            int f = tid + t * 256;
            int row = f >> 3, c4 = f & 7;
            float4 av = *(const float4*)(A + (size_t)(m0 + row) * lda + kt + c4 * 4);
            Ast[c4 * 4 + 0][row] = av.x; Ast[c4 * 4 + 1][row] = av.y;
            Ast[c4 * 4 + 2][row] = av.z; Ast[c4 * 4 + 3][row] = av.w;
        }
#pragma unroll
        for (int t = 0; t < 4; t++) {
            int f = tid + t * 256;
            int row = f >> 5, c4 = f & 31;
            *(float4*)(&Xs[row][c4 * 4]) =
                *(const float4*)(Bm + (size_t)(kt + row) * ldb + n0 + c4 * 4);
        }
        __syncthreads();
#pragma unroll 8
        for (int kk = 0; kk < 32; kk++) {
            float4 a0 = *(const float4*)&Ast[kk][r0];
            float4 a1 = *(const float4*)&Ast[kk][r0 + 4];
            float4 x0 = *(const float4*)&Xs[kk][c0];
            float4 x1 = *(const float4*)&Xs[kk][c0 + 4];
            unsigned long long b0 = pk2(x0.x, x0.y), b1 = pk2(x0.z, x0.w);
            unsigned long long b2 = pk2(x1.x, x1.y), b3 = pk2(x1.z, x1.w);
            float av[8] = { a0.x, a0.y, a0.z, a0.w, a1.x, a1.y, a1.z, a1.w };
#pragma unroll
            for (int i = 0; i < 8; i++) {
                unsigned long long ad = pk2(av[i], av[i]);
                acc[i][0] = f2fma(ad, b0, acc[i][0]);
                acc[i][1] = f2fma(ad, b1, acc[i][1]);
                acc[i][2] = f2fma(ad, b2, acc[i][2]);
                acc[i][3] = f2fma(ad, b3, acc[i][3]);
            }
        }
        __syncthreads();
    }
#pragma unroll
    for (int i = 0; i < 8; i++) {
        int gm = m0 + r0 + i;
        float o[8];
#pragma unroll
        for (int j2 = 0; j2 < 4; j2++) {
            float2 f = upk(acc[i][j2]);
            o[2 * j2] = f.x; o[2 * j2 + 1] = f.y;
        }
        if (epi == 1) {
#pragma unroll
            for (int jj = 0; jj < 8; jj++) o[jj] = gelu_tanh(o[jj] + bias[n0 + c0 + jj]);
        } else if (epi == 2) {
#pragma unroll
            for (int jj = 0; jj < 8; jj++)
                o[jj] = o[jj] + bias[n0 + c0 + jj] + resid[(size_t)gm * ldc + n0 + c0 + jj];
        } else if (epi == 3) {
#pragma unroll
            for (int jj = 0; jj < 8; jj++) o[jj] *= scale;
        }
        *(float4*)(C + (size_t)gm * ldc + n0 + c0)     = make_float4(o[0], o[1], o[2], o[3]);
        *(float4*)(C + (size_t)gm * ldc + n0 + c0 + 4) = make_float4(o[4], o[5], o[6], o[7]);
    }
}

// ---------------- mix ----------------
__global__ void mixed_kernel(const float* __restrict__ st, const float* __restrict__ attnv,
                             float* __restrict__ mixed) {
    int i = blockIdx.x * 256 + threadIdx.x;
    int bh = i >> 17;
    int w = i & 131071;
    size_t base = ((size_t)bh << 18) + w;
    mixed[i] = 0.3f * attnv[i] + 0.7f * st[base];
}

// ---------------- output projection + residual ----------------
__global__ void proj_kernel(const float* __restrict__ mixed, const float* __restrict__ Wo,
                            const float* __restrict__ x, float* __restrict__ x1) {
    __shared__ float Xs[64][65];
    __shared__ float Ws[64][65];
    int s0 = blockIdx.x * 64;
    int bh = blockIdx.y;
    int h = bh % HH, b = bh / HH;
    int tid = threadIdx.x, tx = tid % 16, ty = tid / 16;
    const float* xb = mixed + (((size_t)bh) << 17) + s0;
    const float* Wb = Wo + h * 4096;
    for (int t = tid; t < 1024; t += 256) {
        int d = t >> 4, c4 = t & 15;
        float4 vv = *(const float4*)(xb + (size_t)d * 2048 + c4 * 4);
        Xs[c4 * 4 + 0][d] = vv.x; Xs[c4 * 4 + 1][d] = vv.y;
        Xs[c4 * 4 + 2][d] = vv.z; Xs[c4 * 4 + 3][d] = vv.w;
        float4 wv = *(const float4*)(Wb + (t / 16) * 64 + (t % 16) * 4);
        Ws[t / 16][(t % 16) * 4 + 0] = wv.x; Ws[t / 16][(t % 16) * 4 + 1] = wv.y;
        Ws[t / 16][(t % 16) * 4 + 2] = wv.z; Ws[t / 16][(t % 16) * 4 + 3] = wv.w;
    }
    __syncthreads();
    float acc[4][4] = {};
#pragma unroll 8
    for (int kk = 0; kk < 64; kk++) {
        float xv[4], wv[4];
#pragma unroll
        for (int i = 0; i < 4; i++) xv[i] = Xs[ty * 4 + i][kk];
#pragma unroll
        for (int j = 0; j < 4; j++) wv[j] = Ws[kk][tx * 4 + j];
#pragma unroll
        for (int i = 0; i < 4; i++)
#pragma unroll
            for (int j = 0; j < 4; j++) acc[i][j] += xv[i] * wv[j];
    }
#pragma unroll
    for (int i = 0; i < 4; i++) {
        int srow = s0 + ty * 4 + i;
#pragma unroll
        for (int j = 0; j < 4; j++) {
            int c = tx * 4 + j;
            size_t o = ((size_t)b * SS + srow) * DD + h * 64 + c;
            x1[o] = x[o] + acc[i][j];
        }
    }
}

// ---------------- launch ----------------
extern "C" void kernel_launch(void* const* d_in, const int* in_sizes, int n_in,
                              void* d_out, int out_size) {
    const float* x     = (const float*)d_in[0];
    const float* Wq    = (const float*)d_in[1];
    const float* Wk    = (const float*)d_in[2];
    const float* Wv    = (const float*)d_in[3];
    const float* Wo    = (const float*)d_in[4];
    const float* omega = (const float*)d_in[5];
    const float* g1    = (const float*)d_in[6];
    const float* be1   = (const float*)d_in[7];
    const float* g2    = (const float*)d_in[8];
    const float* be2   = (const float*)d_in[9];
    const float* W1    = (const float*)d_in[10];
    const float* bf1   = (const float*)d_in[11];
    const float* W2    = (const float*)d_in[12];
    const float* bf2   = (const float*)d_in[13];
    float* out = (float*)d_out;

    float *xh, *q, *k, *kT, *A, *st, *apf, *d1, *attnv, *mixed, *x1, *xn2, *hb;
    __nv_bfloat16 *Ahi, *Alo, *sthi, *stlo, *aphi, *aplo;
    cudaGetSymbolAddress((void**)&xh,    g_xh);
    cudaGetSymbolAddress((void**)&q,     g_q);
    cudaGetSymbolAddress((void**)&k,     g_k);
    cudaGetSymbolAddress((void**)&kT,    g_kT);
    cudaGetSymbolAddress((void**)&A,     g_A);
    cudaGetSymbolAddress((void**)&Ahi,   g_Ahi);
    cudaGetSymbolAddress((void**)&Alo,   g_Alo);
    cudaGetSymbolAddress((void**)&st,    g_st);
    cudaGetSymbolAddress((void**)&sthi,  g_sthi);
    cudaGetSymbolAddress((void**)&stlo,  g_stlo);
    cudaGetSymbolAddress((void**)&apf,   g_apf);
    cudaGetSymbolAddress((void**)&aphi,  g_aphi);
    cudaGetSymbolAddress((void**)&aplo,  g_aplo);
    cudaGetSymbolAddress((void**)&d1,    g_d1);
    cudaGetSymbolAddress((void**)&attnv, g_attnv);
    cudaGetSymbolAddress((void**)&mixed, g_mixed);
    cudaGetSymbolAddress((void**)&x1,    g_x1);
    cudaGetSymbolAddress((void**)&xn2,   g_xn2);
    cudaGetSymbolAddress((void**)&hb,    g_hb);

    cudaFuncSetAttribute(apply_fused, cudaFuncAttributeMaxDynamicSharedMemorySize, SMEM_BULK);

    // 1) LN1 -> head layout
    ln_kernel<<<BB * SS, 256>>>(x, g1, be1, xh, 0);
    // 2) QKV
    qkv_kernel<<<dim3(SS / 64, BH), 256>>>(xh, Wq, Wk, Wv, q, k, st, sthi, stlo);
    // 3) k transpose
    transpose_k<<<dim3(SS / 32, HDIM / 32, BH), dim3(32, 8)>>>(k, kT);
    // 4) scores = (q @ kT) * 1/8
    gemm128<<<dim3(SS / 128, SS / 128, BH), 256>>>(
        q, kT, A, SS, SS, HDIM, HDIM, SS, SS,
        (size_t)SS * HDIM, (size_t)HDIM * SS, (size_t)SS * SS,
        3, nullptr, nullptr, 0.125f);
    // 5) softmax -> tiled bf16 hi/lo
    softmax_kernel<<<BH * SS, 256>>>(A, Ahi, Alo);
    // 6) 5 Heun steps, fused apply+eval
    for (int stp = 0; stp < 5; stp++) {
        apply_fused<<<dim3(SS / 128, BH), 256, SMEM_BULK>>>(
            Ahi, Alo, sthi, stlo, st, apf, d1, omega, aphi, aplo, attnv,
            stp == 0 ? 1 : 0);
        apply_fused<<<dim3(SS / 128, BH), 256, SMEM_BULK>>>(
            Ahi, Alo, aphi, aplo, st, apf, d1, omega, sthi, stlo, attnv, 2);
    }
    // 7) mix
    mixed_kernel<<<16384, 256>>>(st, attnv, mixed);
    // 8) output projection + residual
    proj_kernel<<<dim3(SS / 64, BH), 256>>>(mixed, Wo, x, x1);
    // 9) LN2
    ln_kernel<<<BB * SS, 256>>>(x1, g2, be2, xn2, 1);
    // 10) MLP
    gemm128<<<dim3(BB * SS / 128, DFFN / 128, 1), 256>>>(
        xn2, W1, hb, BB * SS, DFFN, DD, DD, DFFN, DFFN,
        0, 0, 0, 1, bf1, nullptr, 1.0f);
    gemm128<<<dim3(BB * SS / 128, DD / 128, 1), 256>>>(
        hb, W2, out, BB * SS, DD, DFFN, DFFN, DD, DD,
        0, 0, 0, 2, bf2, x1, 1.0f);
}

// round 16
// speedup vs baseline: 1.1238x; 1.1238x over previous
#include <cuda_runtime.h>
#include <cuda_bf16.h>
#include <math.h>

#define BB   2
#define SS   2048
#define DD   1024
#define HH   16
#define HDIM 64
#define DFFN 2048
#define BH   (BB*HH)

// ---------------- scratch (static __device__, no allocations) ----------------
__device__ float g_xh [BH*SS*HDIM];
__device__ float g_q  [BH*SS*HDIM];
__device__ float g_k  [BH*SS*HDIM];
__device__ float g_kT [BH*HDIM*SS];
__device__ float g_A  [(size_t)BH*SS*SS];                 // fp32 scores (512 MB)
// A and state bf16 splits live in CHUNK-TILED + SWIZZLED layout (see aidx/sidx)
__device__ __nv_bfloat16 g_Ahi[(size_t)BH*SS*SS];
__device__ __nv_bfloat16 g_Alo[(size_t)BH*SS*SS];
__device__ float         g_st  [(size_t)BH*128*SS];       // linear [bh][n][k]
__device__ __nv_bfloat16 g_sthi[(size_t)BH*128*SS];
__device__ __nv_bfloat16 g_stlo[(size_t)BH*128*SS];
__device__ float         g_apf [(size_t)BH*128*SS];
__device__ __nv_bfloat16 g_aphi[(size_t)BH*128*SS];
__device__ __nv_bfloat16 g_aplo[(size_t)BH*128*SS];
__device__ float         g_z   [(size_t)BH*128*SS];       // apply output, [bh][n][k]
__device__ float         g_d1  [(size_t)BH*128*SS];
__device__ float g_attnv[(size_t)BH*64*SS];
__device__ float g_mixed[(size_t)BH*64*SS];
__device__ float g_x1 [BB*SS*DD];
__device__ float g_xn2[BB*SS*DD];
__device__ float g_hb [(size_t)BB*SS*DFFN];

// ---------------- tiled+swizzled index helpers ----------------
__device__ __forceinline__ size_t aidx(int bh, int m, int k) {
    return ((((size_t)bh * 32 + (k >> 6)) * 2048 + m) * 8 + ((((k >> 3) & 7) ^ (m & 7)))) * 8
           + (k & 7);
}
__device__ __forceinline__ size_t sidx(int bh, int n, int k) {
    return ((((size_t)bh * 32 + (k >> 6)) * 128 + n) * 8 + ((((k >> 3) & 7) ^ (n & 7)))) * 8
           + (k & 7);
}

// ---------------- generic helpers ----------------
__device__ __forceinline__ unsigned long long pk2(float lo, float hi) {
    unsigned long long r;
    asm("mov.b64 %0, {%1,%2};" : "=l"(r) : "f"(lo), "f"(hi));
    return r;
}
__device__ __forceinline__ unsigned long long f2fma(unsigned long long a,
                                                    unsigned long long b,
                                                    unsigned long long c) {
    unsigned long long d;
    asm("fma.rn.f32x2 %0, %1, %2, %3;" : "=l"(d) : "l"(a), "l"(b), "l"(c));
    return d;
}
__device__ __forceinline__ float2 upk(unsigned long long v) {
    float2 f;
    asm("mov.b64 {%0,%1}, %2;" : "=f"(f.x), "=f"(f.y) : "l"(v));
    return f;
}
__device__ __forceinline__ float gelu_tanh(float x) {
    float x3 = x * x * x;
    return 0.5f * x * (1.0f + tanhf(0.7978845608028654f * (x + 0.044715f * x3)));
}
__device__ __forceinline__ float blockReduceSum(float v, float* sdata) {
    int tid = threadIdx.x;
    sdata[tid] = v; __syncthreads();
    for (int s = 128; s > 0; s >>= 1) {
        if (tid < s) sdata[tid] += sdata[tid + s];
        __syncthreads();
    }
    float r = sdata[0]; __syncthreads();
    return r;
}
__device__ __forceinline__ float blockReduceMax(float v, float* sdata) {
    int tid = threadIdx.x;
    sdata[tid] = v; __syncthreads();
    for (int s = 128; s > 0; s >>= 1) {
        if (tid < s) sdata[tid] = fmaxf(sdata[tid], sdata[tid + s]);
        __syncthreads();
    }
    float r = sdata[0]; __syncthreads();
    return r;
}
__device__ __forceinline__ void split_bf16(float v, __nv_bfloat16& hi, __nv_bfloat16& lo) {
    hi = __float2bfloat16(v);
    lo = __float2bfloat16(v - __bfloat162float(hi));
}
__device__ __forceinline__ unsigned int s2u(const void* p) {
    unsigned int a;
    asm("{ .reg .u64 t; cvta.to.shared.u64 t, %1; cvt.u32.u64 %0, t; }" : "=r"(a) : "l"(p));
    return a;
}

// ---------------- warp-mma + async-bulk helpers ----------------
__device__ __forceinline__ void ldmx4(unsigned int* r, unsigned int addr) {
    asm volatile("ldmatrix.sync.aligned.m8n8.x4.shared.b16 {%0,%1,%2,%3}, [%4];"
                 : "=r"(r[0]), "=r"(r[1]), "=r"(r[2]), "=r"(r[3]) : "r"(addr));
}
__device__ __forceinline__ void mma16816(float* c, const unsigned int* a,
                                         const unsigned int b0, const unsigned int b1) {
    asm volatile(
        "mma.sync.aligned.m16n8k16.row.col.f32.bf16.bf16.f32 "
        "{%0,%1,%2,%3}, {%4,%5,%6,%7}, {%8,%9}, {%0,%1,%2,%3};"
        : "+f"(c[0]), "+f"(c[1]), "+f"(c[2]), "+f"(c[3])
        : "r"(a[0]), "r"(a[1]), "r"(a[2]), "r"(a[3]), "r"(b0), "r"(b1));
}
__device__ __forceinline__ void bulk_cp(unsigned int dst, const void* src,
                                        unsigned int bytes, unsigned int mbar) {
    asm volatile(
        "cp.async.bulk.shared::cta.global.mbarrier::complete_tx::bytes [%0], [%1], %2, [%3];"
        :: "r"(dst), "l"(src), "r"(bytes), "r"(mbar) : "memory");
}
__device__ __forceinline__ void mbar_init(unsigned int mbar, unsigned int cnt) {
    asm volatile("mbarrier.init.shared.b64 [%0], %1;" :: "r"(mbar), "r"(cnt) : "memory");
}
__device__ __forceinline__ void mbar_expect(unsigned int mbar, unsigned int bytes) {
    asm volatile("mbarrier.arrive.expect_tx.shared.b64 _, [%0], %1;"
                 :: "r"(mbar), "r"(bytes) : "memory");
}
__device__ __forceinline__ void mbar_wait(unsigned int mbar, unsigned int parity) {
    asm volatile(
        "{\n\t"
        ".reg .pred P1;\n\t"
        "LAB_WAIT_%=:\n\t"
        "mbarrier.try_wait.parity.acquire.cta.shared::cta.b64 P1, [%0], %1, 0x989680;\n\t"
        "@P1 bra.uni DONE_%=;\n\t"
        "bra.uni LAB_WAIT_%=;\n\t"
        "DONE_%=:\n\t"
        "}"
        :: "r"(mbar), "r"(parity) : "memory");
}

// ---------------- LayerNorm ----------------
__global__ void ln_kernel(const float* __restrict__ x, const float* __restrict__ g,
                          const float* __restrict__ be, float* __restrict__ out, int mode) {
    __shared__ float sred[256];
    int row = blockIdx.x;
    int tid = threadIdx.x;
    const float* xr = x + (size_t)row * DD;
    float v[4];
    float s = 0.f;
#pragma unroll
    for (int kk = 0; kk < 4; kk++) { v[kk] = xr[tid + 256 * kk]; s += v[kk]; }
    s = blockReduceSum(s, sred);
    float mean = s * (1.0f / DD);
    float qv = 0.f;
#pragma unroll
    for (int kk = 0; kk < 4; kk++) { float d = v[kk] - mean; qv += d * d; }
    qv = blockReduceSum(qv, sred);
    float inv = rsqrtf(qv * (1.0f / DD) + 1e-5f);
    int b = row / SS, sidx_ = row % SS;
#pragma unroll
    for (int kk = 0; kk < 4; kk++) {
        int j = tid + 256 * kk;
        float y = (v[kk] - mean) * inv * g[j] + be[j];
        if (mode == 0) {
            int h = j >> 6, d = j & 63;
            out[(((size_t)(b * HH + h)) * SS + sidx_) * HDIM + d] = y;
        } else {
            out[(size_t)row * DD + j] = y;
        }
    }
}

// ---------------- QKV projection ----------------
__global__ void qkv_kernel(const float* __restrict__ xh, const float* __restrict__ Wq,
                           const float* __restrict__ Wk, const float* __restrict__ Wv,
                           float* __restrict__ qo, float* __restrict__ ko,
                           float* __restrict__ stf, __nv_bfloat16* __restrict__ sthi,
                           __nv_bfloat16* __restrict__ stlo) {
    __shared__ float Xs[64][65];
    __shared__ float Ws[64][65];
    int s0 = blockIdx.x * 64;
    int bh = blockIdx.y;
    int h = bh % HH;
    int tid = threadIdx.x, tx = tid % 16, ty = tid / 16;
    const float* xb = xh + ((size_t)bh * SS + s0) * HDIM;
    for (int t = tid; t < 1024; t += 256) {
        int r = t / 16, c4 = t % 16;
        float4 vv = *(const float4*)(xb + r * 64 + c4 * 4);
        Xs[r][c4 * 4 + 0] = vv.x; Xs[r][c4 * 4 + 1] = vv.y;
        Xs[r][c4 * 4 + 2] = vv.z; Xs[r][c4 * 4 + 3] = vv.w;
    }
    const float* Wm[3] = { Wq + h * 4096, Wk + h * 4096, Wv + h * 4096 };
    for (int m = 0; m < 3; m++) {
        __syncthreads();
        for (int t = tid; t < 1024; t += 256) {
            int r = t / 16, c4 = t % 16;
            float4 vv = *(const float4*)(Wm[m] + r * 64 + c4 * 4);
            Ws[r][c4 * 4 + 0] = vv.x; Ws[r][c4 * 4 + 1] = vv.y;
            Ws[r][c4 * 4 + 2] = vv.z; Ws[r][c4 * 4 + 3] = vv.w;
        }
        __syncthreads();
        float acc[4][4] = {};
#pragma unroll 8
        for (int kk = 0; kk < 64; kk++) {
            float xv[4], wv[4];
#pragma unroll
            for (int i = 0; i < 4; i++) xv[i] = Xs[ty * 4 + i][kk];
#pragma unroll
            for (int j = 0; j < 4; j++) wv[j] = Ws[kk][tx * 4 + j];
#pragma unroll
            for (int i = 0; i < 4; i++)
#pragma unroll
                for (int j = 0; j < 4; j++) acc[i][j] += xv[i] * wv[j];
        }
#pragma unroll
        for (int i = 0; i < 4; i++) {
            int srow = s0 + ty * 4 + i;
            size_t base = (size_t)bh * SS + srow;
#pragma unroll
            for (int j = 0; j < 4; j++) {
                int c = tx * 4 + j;
                if (m == 0)      qo[base * HDIM + c] = acc[i][j];
                else if (m == 1) ko[base * HDIM + c] = acc[i][j];
                else {
                    float v = acc[i][j];
                    __nv_bfloat16 hi, lo; split_bf16(v, hi, lo);
                    size_t lb = ((size_t)bh << 18) + ((size_t)c << 11) + srow;
                    stf[lb] = v; stf[lb + 131072] = 0.f;
                    size_t th = sidx(bh, c, srow), tb = sidx(bh, c + 64, srow);
                    sthi[th] = hi; stlo[th] = lo;
                    sthi[tb] = __float2bfloat16(0.f);
                    stlo[tb] = __float2bfloat16(0.f);
                }
            }
        }
    }
}

// ---------------- k transpose ----------------
__global__ void transpose_k(const float* __restrict__ k, float* __restrict__ kT) {
    __shared__ float t[32][33];
    int s0 = blockIdx.x * 32, d0 = blockIdx.y * 32, bh = blockIdx.z;
    const float* kb = k + (size_t)bh * SS * HDIM;
    float* kTb = kT + (size_t)bh * HDIM * SS;
    for (int r = threadIdx.y; r < 32; r += 8)
        t[r][threadIdx.x] = kb[(size_t)(s0 + r) * HDIM + d0 + threadIdx.x];
    __syncthreads();
    for (int r = threadIdx.y; r < 32; r += 8)
        kTb[(size_t)(d0 + r) * SS + s0 + threadIdx.x] = t[threadIdx.x][r];
}

// ---------------- row softmax -> bf16 hi/lo in tiled layout ----------------
__global__ void softmax_kernel(const float* __restrict__ A,
                               __nv_bfloat16* __restrict__ Ahi,
                               __nv_bfloat16* __restrict__ Alo) {
    __shared__ float sred[256];
    size_t rb = (size_t)blockIdx.x * SS;
    const float* ar = A + rb;
    int bh = blockIdx.x >> 11, m = blockIdx.x & 2047;
    int tid = threadIdx.x;
    float r[8];
    float mx = -1e30f;
#pragma unroll
    for (int kk = 0; kk < 8; kk++) { r[kk] = ar[tid + 256 * kk]; mx = fmaxf(mx, r[kk]); }
    mx = blockReduceMax(mx, sred);
    float s = 0.f;
#pragma unroll
    for (int kk = 0; kk < 8; kk++) { r[kk] = __expf(r[kk] - mx); s += r[kk]; }
    s = blockReduceSum(s, sred);
    float inv = 1.0f / s;
#pragma unroll
    for (int kk = 0; kk < 8; kk++) {
        float val = r[kk] * inv;
        __nv_bfloat16 hi, lo; split_bf16(val, hi, lo);
        size_t ai = aidx(bh, m, tid + 256 * kk);
        Ahi[ai] = hi;
        Alo[ai] = lo;
    }
}

// ---------------- HMMA A-apply, cp.async.bulk 3-stage pipeline ----------------
// Z[bh][n][k=seq] = sum_t A[bh][m][t] * S[bh][n][t]; CTA 128m x 128n, 8 warps 64x32.
#define STAGE_B 65536
#define SMEM_BULK (128 + 3 * STAGE_B)   // 196736
__global__ void __launch_bounds__(256) apply_mma(
    const __nv_bfloat16* __restrict__ Ahi, const __nv_bfloat16* __restrict__ Alo,
    const __nv_bfloat16* __restrict__ Bhi, const __nv_bfloat16* __restrict__ Blo,
    float* __restrict__ Zt)
{
    extern __shared__ char smem[];
    unsigned int sb = s2u(smem);
    int tid = threadIdx.x, wid = tid >> 5, lane = tid & 31;
    int m0 = blockIdx.x << 7;
    int bh = blockIdx.y;
    int wm = (wid >> 2) * 64, wn = (wid & 3) * 32;

    unsigned int mb[3] = { sb, sb + 8, sb + 16 };
    if (tid == 0) { mbar_init(mb[0], 1); mbar_init(mb[1], 1); mbar_init(mb[2], 1); }
    __syncthreads();

    const char* pAh = (const char*)Ahi;
    const char* pAl = (const char*)Alo;
    const char* pBh = (const char*)Bhi;
    const char* pBl = (const char*)Blo;

    float c[4][4][4];
#pragma unroll
    for (int i = 0; i < 4; i++)
#pragma unroll
        for (int j = 0; j < 4; j++)
#pragma unroll
            for (int r = 0; r < 4; r++) c[i][j][r] = 0.f;

    int arow = ((lane >> 3) & 1) * 8 + (lane & 7);
    int brow = (lane >> 4) * 8 + (lane & 7);
    int ua = (lane >> 4);
    int ub = ((lane >> 3) & 1);
    int rx = lane & 7;
    unsigned int aRow = (wm + arow) * 128;
    unsigned int bRow = (wn + brow) * 128;

    // prologue: issue chunks 0,1,2 into stages 0,1,2
    if (tid == 0) {
#pragma unroll
        for (int p = 0; p < 3; p++) {
            mbar_expect(mb[p], 4 * 16384);
            unsigned int dst = sb + 128 + p * STAGE_B;
            size_t aoff = (((size_t)bh * 32 + p) * 2048 + m0) * 128;
            size_t boff = (((size_t)bh * 32 + p) * 128) * 128;
            bulk_cp(dst,          pAh + aoff, 16384, mb[p]);
            bulk_cp(dst + 16384,  pAl + aoff, 16384, mb[p]);
            bulk_cp(dst + 32768,  pBh + boff, 16384, mb[p]);
            bulk_cp(dst + 49152,  pBl + boff, 16384, mb[p]);
        }
    }

    for (int ck = 0; ck < 32; ck++) {
        int s = ck % 3;
        mbar_wait(mb[s], (ck / 3) & 1);

        unsigned int base = sb + 128 + s * STAGE_B;
#pragma unroll
        for (int ks = 0; ks < 4; ks++) {
            unsigned int au = (unsigned int)(((ua + 2 * ks) ^ rx) << 4);
            unsigned int bu = (unsigned int)(((ub + 2 * ks) ^ rx) << 4);
            unsigned int a[4][4];
            unsigned int b[2][4];
            // --- Ah x Bh ---
#pragma unroll
            for (int ma = 0; ma < 4; ma++) ldmx4(a[ma], base + aRow + ma * 2048 + au);
#pragma unroll
            for (int p = 0; p < 2; p++) ldmx4(b[p], base + 32768 + bRow + p * 2048 + bu);
#pragma unroll
            for (int ma = 0; ma < 4; ma++)
#pragma unroll
                for (int na = 0; na < 4; na++)
                    mma16816(c[ma][na], a[ma], b[na >> 1][(na & 1) * 2],
                             b[na >> 1][(na & 1) * 2 + 1]);
            // --- Al x Bh ---
#pragma unroll
            for (int ma = 0; ma < 4; ma++)
                ldmx4(a[ma], base + 16384 + aRow + ma * 2048 + au);
#pragma unroll
            for (int ma = 0; ma < 4; ma++)
#pragma unroll
                for (int na = 0; na < 4; na++)
                    mma16816(c[ma][na], a[ma], b[na >> 1][(na & 1) * 2],
                             b[na >> 1][(na & 1) * 2 + 1]);
            // --- Ah x Bl ---
#pragma unroll
            for (int ma = 0; ma < 4; ma++) ldmx4(a[ma], base + aRow + ma * 2048 + au);
#pragma unroll
            for (int p = 0; p < 2; p++)
                ldmx4(b[p], base + 49152 + bRow + p * 2048 + bu);
#pragma unroll
            for (int ma = 0; ma < 4; ma++)
#pragma unroll
                for (int na = 0; na < 4; na++)
                    mma16816(c[ma][na], a[ma], b[na >> 1][(na & 1) * 2],
                             b[na >> 1][(na & 1) * 2 + 1]);
        }
        __syncthreads();
        if (tid == 0 && ck + 3 < 32) {
            mbar_expect(mb[s], 4 * 16384);
            unsigned int dst = sb + 128 + s * STAGE_B;
            size_t aoff = (((size_t)bh * 32 + (ck + 3)) * 2048 + m0) * 128;
            size_t boff = (((size_t)bh * 32 + (ck + 3)) * 128) * 128;
            bulk_cp(dst,          pAh + aoff, 16384, mb[s]);
            bulk_cp(dst + 16384,  pAl + aoff, 16384, mb[s]);
            bulk_cp(dst + 32768,  pBh + boff, 16384, mb[s]);
            bulk_cp(dst + 49152,  pBl + boff, 16384, mb[s]);
        }
    }

    // epilogue: c frags {c0:(g,2tg), c1:(g,2tg+1), c2:(g+8,2tg), c3:(g+8,2tg+1)}
    int g = lane >> 2, tg = lane & 3;
    size_t zb = (((size_t)bh) << 18) + m0;
#pragma unroll
    for (int ma = 0; ma < 4; ma++) {
        int mloc = wm + ma * 16 + g;
#pragma unroll
        for (int na = 0; na < 4; na++) {
            int nloc = wn + na * 8 + tg * 2;
            float* p = Zt + zb + ((size_t)nloc << 11) + mloc;
            p[0]          = c[ma][na][0];
            p[2048]       = c[ma][na][1];
            p[8]          = c[ma][na][2];
            p[2048 + 8]   = c[ma][na][3];
        }
    }
}

// ---------------- fp32x2 GEMM (scores + MLP) ----------------
__global__ void __launch_bounds__(256, 2) gemm128(
    const float* __restrict__ A, const float* __restrict__ Bm, float* __restrict__ C,
    int M, int N, int K, int lda, int ldb, int ldc,
    size_t sA, size_t sB, size_t sC,
    int epi, const float* __restrict__ bias, const float* __restrict__ resid, float scale) {
    A  += (size_t)blockIdx.z * sA;
    Bm += (size_t)blockIdx.z * sB;
    C  += (size_t)blockIdx.z * sC;
    __shared__ float Ast[32][132];
    __shared__ float Xs[32][128];
    int m0 = blockIdx.x * 128, n0 = blockIdx.y * 128;
    int tid = threadIdx.x, tx = tid % 16, ty = tid / 16;
    int r0 = ty * 8, c0 = tx * 8;
    unsigned long long acc[8][4] = {};

    for (int kt = 0; kt < K; kt += 32) {
#pragma unroll
        for (int t = 0; t < 4; t++) {
            int f = tid + t * 256;
            int row = f >> 3, c4 = f & 7;
            float4 av = *(const float4*)(A + (size_t)(m0 + row) * lda + kt + c4 * 4);
            Ast[c4 * 4 + 0][row] = av.x; Ast[c4 * 4 + 1][row] = av.y;
            Ast[c4 * 4 + 2][row] = av.z; Ast[c4 * 4 + 3][row] = av.w;
        }
#pragma unroll
        for (int t = 0; t < 4; t++) {
            int f = tid + t * 256;
            int row = f >> 5, c4 = f & 31;
            *(float4*)(&Xs[row][c4 * 4]) =
                *(const float4*)(Bm + (size_t)(kt + row) * ldb + n0 + c4 * 4);
        }
        __syncthreads();
#pragma unroll 8
        for (int kk = 0; kk < 32; kk++) {
            float4 a0 = *(const float4*)&Ast[kk][r0];
            float4 a1 = *(const float4*)&Ast[kk][r0 + 4];
            float4 x0 = *(const float4*)&Xs[kk][c0];
            float4 x1 = *(const float4*)&Xs[kk][c0 + 4];
            unsigned long long b0 = pk2(x0.x, x0.y), b1 = pk2(x0.z, x0.w);
            unsigned long long b2 = pk2(x1.x, x1.y), b3 = pk2(x1.z, x1.w);
            float av[8] = { a0.x, a0.y, a0.z, a0.w, a1.x, a1.y, a1.z, a1.w };
#pragma unroll
            for (int i = 0; i < 8; i++) {
                unsigned long long ad = pk2(av[i], av[i]);
                acc[i][0] = f2fma(ad, b0, acc[i][0]);
                acc[i][1] = f2fma(ad, b1, acc[i][1]);
                acc[i][2] = f2fma(ad, b2, acc[i][2]);
                acc[i][3] = f2fma(ad, b3, acc[i][3]);
            }
        }
        __syncthreads();
    }
#pragma unroll
    for (int i = 0; i < 8; i++) {
        int gm = m0 + r0 + i;
        float o[8];
#pragma unroll
        for (int j2 = 0; j2 < 4; j2++) {
            float2 f = upk(acc[i][j2]);
            o[2 * j2] = f.x; o[2 * j2 + 1] = f.y;
        }
        if (epi == 1) {
#pragma unroll
            for (int jj = 0; jj < 8; jj++) o[jj] = gelu_tanh(o[jj] + bias[n0 + c0 + jj]);
        } else if (epi == 2) {
#pragma unroll
            for (int jj = 0; jj < 8; jj++)
                o[jj] = o[jj] + bias[n0 + c0 + jj] + resid[(size_t)gm * ldc + n0 + c0 + jj];
        } else if (epi == 3) {
#pragma unroll
            for (int jj = 0; jj < 8; jj++) o[jj] *= scale;
        }
        *(float4*)(C + (size_t)gm * ldc + n0 + c0)     = make_float4(o[0], o[1], o[2], o[3]);
        *(float4*)(C + (size_t)gm * ldc + n0 + c0 + 4) = make_float4(o[4], o[5], o[6], o[7]);
    }
}

// ---------------- ODE elementwise (fp32 linear layout; bf16 splits tiled) ----------------
#define CA 0.99500416527802576610f
#define SA 0.09983341664682815230f

__global__ void eval1_kernel(const float* __restrict__ st, const float* __restrict__ z,
                             const float* __restrict__ omega, float* __restrict__ d1,
                             float* __restrict__ apf, __nv_bfloat16* __restrict__ aphi,
                             __nv_bfloat16* __restrict__ aplo,
                             float* __restrict__ attnv, int first) {
    int i = blockIdx.x * 256 + threadIdx.x;
    int bh = i >> 17;
    int w = i & 131071;
    int d = w >> 11;
    int k = w & 2047;
    size_t base = ((size_t)bh << 18) + ((size_t)d << 11) + k;
    size_t bb = base + 131072;
    float a = st[base], b = st[bb];
    float za = z[base], zb = z[bb];
    float om = omega[((bh & (HH - 1)) << 6) + d];
    float r2 = a * a + b * b;
    float ra = za * CA + zb * SA;
    float rb = zb * CA - za * SA;
    float da = (1.0f - r2) * a - om * b + 3.0f * (ra - a);
    float db = (1.0f - r2) * b + om * a + 3.0f * (rb - b);
    d1[base] = da; d1[bb] = db;
    float apv = a + 0.02f * da, bpv = b + 0.02f * db;
    apf[base] = apv; apf[bb] = bpv;
    __nv_bfloat16 hi, lo;
    size_t th = sidx(bh, d, k), tb = sidx(bh, d + 64, k);
    split_bf16(apv, hi, lo); aphi[th] = hi; aplo[th] = lo;
    split_bf16(bpv, hi, lo); aphi[tb] = hi; aplo[tb] = lo;
    if (first) attnv[i] = za;
}

__global__ void eval2_kernel(float* __restrict__ st, const float* __restrict__ apf,
                             const float* __restrict__ z, const float* __restrict__ d1,
                             const float* __restrict__ omega,
                             __nv_bfloat16* __restrict__ sthi, __nv_bfloat16* __restrict__ stlo) {
    int i = blockIdx.x * 256 + threadIdx.x;
    int bh = i >> 17;
    int w = i & 131071;
    int d = w >> 11;
    int k = w & 2047;
    size_t base = ((size_t)bh << 18) + ((size_t)d << 11) + k;
    size_t bb = base + 131072;
    float a = st[base], b = st[bb];
    float ap = apf[base], bp = apf[bb];
    float zap = z[base], zbp = z[bb];
    float da1 = d1[base], db1 = d1[bb];
    float om = omega[((bh & (HH - 1)) << 6) + d];
    float r2 = ap * ap + bp * bp;
    float ra = zap * CA + zbp * SA;
    float rb = zbp * CA - zap * SA;
    float da2 = (1.0f - r2) * ap - om * bp + 3.0f * (ra - ap);
    float db2 = (1.0f - r2) * bp + om * ap + 3.0f * (rb - bp);
    float na = a + 0.01f * (da1 + da2);
    float nb = b + 0.01f * (db1 + db2);
    st[base] = na; st[bb] = nb;
    __nv_bfloat16 hi, lo;
    size_t th = sidx(bh, d, k), tb = sidx(bh, d + 64, k);
    split_bf16(na, hi, lo); sthi[th] = hi; stlo[th] = lo;
    split_bf16(nb, hi, lo); sthi[tb] = hi; stlo[tb] = lo;
}

__global__ void mixed_kernel(const float* __restrict__ st, const float* __restrict__ attnv,
                             float* __restrict__ mixed) {
    int i = blockIdx.x * 256 + threadIdx.x;
    int bh = i >> 17;
    int w = i & 131071;
    size_t base = ((size_t)bh << 18) + w;
    mixed[i] = 0.3f * attnv[i] + 0.7f * st[base];
}

// ---------------- output projection + residual ----------------
__global__ void proj_kernel(const float* __restrict__ mixed, const float* __restrict__ Wo,
                            const float* __restrict__ x, float* __restrict__ x1) {
    __shared__ float Xs[64][65];
    __shared__ float Ws[64][65];
    int s0 = blockIdx.x * 64;
    int bh = blockIdx.y;
    int h = bh % HH, b = bh / HH;
    int tid = threadIdx.x, tx = tid % 16, ty = tid / 16;
    const float* xb = mixed + (((size_t)bh) << 17) + s0;
    const float* Wb = Wo + h * 4096;
    for (int t = tid; t < 1024; t += 256) {
        int d = t >> 4, c4 = t & 15;
        float4 vv = *(const float4*)(xb + (size_t)d * 2048 + c4 * 4);
        Xs[c4 * 4 + 0][d] = vv.x; Xs[c4 * 4 + 1][d] = vv.y;
        Xs[c4 * 4 + 2][d] = vv.z; Xs[c4 * 4 + 3][d] = vv.w;
        float4 wv = *(const float4*)(Wb + (t / 16) * 64 + (t % 16) * 4);
        Ws[t / 16][(t % 16) * 4 + 0] = wv.x; Ws[t / 16][(t % 16) * 4 + 1] = wv.y;
        Ws[t / 16][(t % 16) * 4 + 2] = wv.z; Ws[t / 16][(t % 16) * 4 + 3] = wv.w;
    }
    __syncthreads();
    float acc[4][4] = {};
#pragma unroll 8
    for (int kk = 0; kk < 64; kk++) {
        float xv[4], wv[4];
#pragma unroll
        for (int i = 0; i < 4; i++) xv[i] = Xs[ty * 4 + i][kk];
#pragma unroll
        for (int j = 0; j < 4; j++) wv[j] = Ws[kk][tx * 4 + j];
#pragma unroll
        for (int i = 0; i < 4; i++)
#pragma unroll
            for (int j = 0; j < 4; j++) acc[i][j] += xv[i] * wv[j];
    }
#pragma unroll
    for (int i = 0; i < 4; i++) {
        int srow = s0 + ty * 4 + i;
#pragma unroll
        for (int j = 0; j < 4; j++) {
            int c = tx * 4 + j;
            size_t o = ((size_t)b * SS + srow) * DD + h * 64 + c;
            x1[o] = x[o] + acc[i][j];
        }
    }
}

// ---------------- launch ----------------
extern "C" void kernel_launch(void* const* d_in, const int* in_sizes, int n_in,
                              void* d_out, int out_size) {
    const float* x     = (const float*)d_in[0];
    const float* Wq    = (const float*)d_in[1];
    const float* Wk    = (const float*)d_in[2];
    const float* Wv    = (const float*)d_in[3];
    const float* Wo    = (const float*)d_in[4];
    const float* omega = (const float*)d_in[5];
    const float* g1    = (const float*)d_in[6];
    const float* be1   = (const float*)d_in[7];
    const float* g2    = (const float*)d_in[8];
    const float* be2   = (const float*)d_in[9];
    const float* W1    = (const float*)d_in[10];
    const float* bf1   = (const float*)d_in[11];
    const float* W2    = (const float*)d_in[12];
    const float* bf2   = (const float*)d_in[13];
    float* out = (float*)d_out;

    float *xh, *q, *k, *kT, *A, *st, *apf, *z, *d1, *attnv, *mixed, *x1, *xn2, *hb;
    __nv_bfloat16 *Ahi, *Alo, *sthi, *stlo, *aphi, *aplo;
    cudaGetSymbolAddress((void**)&xh,    g_xh);
    cudaGetSymbolAddress((void**)&q,     g_q);
    cudaGetSymbolAddress((void**)&k,     g_k);
    cudaGetSymbolAddress((void**)&kT,    g_kT);
    cudaGetSymbolAddress((void**)&A,     g_A);
    cudaGetSymbolAddress((void**)&Ahi,   g_Ahi);
    cudaGetSymbolAddress((void**)&Alo,   g_Alo);
    cudaGetSymbolAddress((void**)&st,    g_st);
    cudaGetSymbolAddress((void**)&sthi,  g_sthi);
    cudaGetSymbolAddress((void**)&stlo,  g_stlo);
    cudaGetSymbolAddress((void**)&apf,   g_apf);
    cudaGetSymbolAddress((void**)&aphi,  g_aphi);
    cudaGetSymbolAddress((void**)&aplo,  g_aplo);
    cudaGetSymbolAddress((void**)&z,     g_z);
    cudaGetSymbolAddress((void**)&d1,    g_d1);
    cudaGetSymbolAddress((void**)&attnv, g_attnv);
    cudaGetSymbolAddress((void**)&mixed, g_mixed);
    cudaGetSymbolAddress((void**)&x1,    g_x1);
    cudaGetSymbolAddress((void**)&xn2,   g_xn2);
    cudaGetSymbolAddress((void**)&hb,    g_hb);

    cudaFuncSetAttribute(apply_mma, cudaFuncAttributeMaxDynamicSharedMemorySize, SMEM_BULK);

    // 1) LN1 -> head layout
    ln_kernel<<<BB * SS, 256>>>(x, g1, be1, xh, 0);
    // 2) QKV
    qkv_kernel<<<dim3(SS / 64, BH), 256>>>(xh, Wq, Wk, Wv, q, k, st, sthi, stlo);
    // 3) k transpose
    transpose_k<<<dim3(SS / 32, HDIM / 32, BH), dim3(32, 8)>>>(k, kT);
    // 4) scores = (q @ kT) * 1/8
    gemm128<<<dim3(SS / 128, SS / 128, BH), 256>>>(
        q, kT, A, SS, SS, HDIM, HDIM, SS, SS,
        (size_t)SS * HDIM, (size_t)HDIM * SS, (size_t)SS * SS,
        3, nullptr, nullptr, 0.125f);
    // 5) softmax -> tiled bf16 hi/lo
    softmax_kernel<<<BH * SS, 256>>>(A, Ahi, Alo);
    // 6) 5 Heun steps, 3-stage bulk-pipelined HMMA A-applies
    for (int stp = 0; stp < 5; stp++) {
        apply_mma<<<dim3(SS / 128, BH), 256, SMEM_BULK>>>(Ahi, Alo, sthi, stlo, z);
        eval1_kernel<<<16384, 256>>>(st, z, omega, d1, apf, aphi, aplo, attnv,
                                     stp == 0 ? 1 : 0);
        apply_mma<<<dim3(SS / 128, BH), 256, SMEM_BULK>>>(Ahi, Alo, aphi, aplo, z);
        eval2_kernel<<<16384, 256>>>(st, apf, z, d1, omega, sthi, stlo);
    }
    // 7) mix
    mixed_kernel<<<16384, 256>>>(st, attnv, mixed);
    // 8) output projection + residual
    proj_kernel<<<dim3(SS / 64, BH), 256>>>(mixed, Wo, x, x1);
    // 9) LN2
    ln_kernel<<<BB * SS, 256>>>(x1, g2, be2, xn2, 1);
    // 10) MLP
    gemm128<<<dim3(BB * SS / 128, DFFN / 128, 1), 256>>>(
        xn2, W1, hb, BB * SS, DFFN, DD, DD, DFFN, DFFN,
        0, 0, 0, 1, bf1, nullptr, 1.0f);
    gemm128<<<dim3(BB * SS / 128, DD / 128, 1), 256>>>(
        hb, W2, out, BB * SS, DD, DFFN, DFFN, DD, DD,
        0, 0, 0, 2, bf2, x1, 1.0f);
}

// round 17
// speedup vs baseline: 1.3824x; 1.2301x over previous
#include <cuda_runtime.h>
#include <cuda_bf16.h>
#include <math.h>

#define BB   2
#define SS   2048
#define DD   1024
#define HH   16
#define HDIM 64
#define DFFN 2048
#define BH   (BB*HH)

// ---------------- scratch (static __device__, no allocations) ----------------
__device__ float g_xh [BH*SS*HDIM];
__device__ float g_A  [(size_t)BH*SS*SS];                 // fp32 scores (512 MB)
__device__ __nv_bfloat16 g_Ahi[(size_t)BH*SS*SS];
__device__ __nv_bfloat16 g_Alo[(size_t)BH*SS*SS];
// q/k bf16 splits, [bh][s][64] rows swizzled (8 units of 16B, unit ^= s&7)
__device__ __nv_bfloat16 g_qhi[BH*SS*HDIM];
__device__ __nv_bfloat16 g_qlo[BH*SS*HDIM];
__device__ __nv_bfloat16 g_khi[BH*SS*HDIM];
__device__ __nv_bfloat16 g_klo[BH*SS*HDIM];
// state in [bh][n(128)][k] linear fp32; bf16 splits chunk-tiled+swizzled (sidx)
__device__ float         g_st  [(size_t)BH*128*SS];
__device__ __nv_bfloat16 g_sthi[(size_t)BH*128*SS];
__device__ __nv_bfloat16 g_stlo[(size_t)BH*128*SS];
__device__ float         g_apf [(size_t)BH*128*SS];
__device__ __nv_bfloat16 g_aphi[(size_t)BH*128*SS];
__device__ __nv_bfloat16 g_aplo[(size_t)BH*128*SS];
__device__ float         g_z   [(size_t)BH*128*SS];
__device__ float         g_d1  [(size_t)BH*128*SS];
__device__ float g_attnv[(size_t)BH*64*SS];
__device__ float g_mixed[(size_t)BH*64*SS];
__device__ float g_x1 [BB*SS*DD];
// MLP operands (bf16 splits, rows swizzled)
__device__ __nv_bfloat16 g_xn2hi[BB*SS*DD];
__device__ __nv_bfloat16 g_xn2lo[BB*SS*DD];
__device__ __nv_bfloat16 g_w1thi[DFFN*DD];
__device__ __nv_bfloat16 g_w1tlo[DFFN*DD];
__device__ __nv_bfloat16 g_w2thi[DD*DFFN];
__device__ __nv_bfloat16 g_w2tlo[DD*DFFN];
__device__ __nv_bfloat16 g_hbhi[(size_t)BB*SS*DFFN];
__device__ __nv_bfloat16 g_hblo[(size_t)BB*SS*DFFN];

// ---------------- index helpers ----------------
__device__ __forceinline__ size_t aidx(int bh, int m, int k) {
    return ((((size_t)bh * 32 + (k >> 6)) * 2048 + m) * 8 + ((((k >> 3) & 7) ^ (m & 7)))) * 8
           + (k & 7);
}
__device__ __forceinline__ size_t sidx(int bh, int n, int k) {
    return ((((size_t)bh * 32 + (k >> 6)) * 128 + n) * 8 + ((((k >> 3) & 7) ^ (n & 7)))) * 8
           + (k & 7);
}
// generic row-swizzled addr: row of nu units (16B each), logical unit u, elem e
__device__ __forceinline__ size_t rswz(int row, int nu, int u, int e) {
    return ((size_t)row * nu + ((u & ~7) | ((u ^ row) & 7))) * 8 + e;
}

// ---------------- generic helpers ----------------
__device__ __forceinline__ float gelu_tanh(float x) {
    float x3 = x * x * x;
    return 0.5f * x * (1.0f + tanhf(0.7978845608028654f * (x + 0.044715f * x3)));
}
__device__ __forceinline__ float blockReduceSum(float v, float* sdata) {
    int tid = threadIdx.x;
    sdata[tid] = v; __syncthreads();
    for (int s = 128; s > 0; s >>= 1) {
        if (tid < s) sdata[tid] += sdata[tid + s];
        __syncthreads();
    }
    float r = sdata[0]; __syncthreads();
    return r;
}
__device__ __forceinline__ float blockReduceMax(float v, float* sdata) {
    int tid = threadIdx.x;
    sdata[tid] = v; __syncthreads();
    for (int s = 128; s > 0; s >>= 1) {
        if (tid < s) sdata[tid] = fmaxf(sdata[tid], sdata[tid + s]);
        __syncthreads();
    }
    float r = sdata[0]; __syncthreads();
    return r;
}
__device__ __forceinline__ void split_bf16(float v, __nv_bfloat16& hi, __nv_bfloat16& lo) {
    hi = __float2bfloat16(v);
    lo = __float2bfloat16(v - __bfloat162float(hi));
}
__device__ __forceinline__ unsigned int s2u(const void* p) {
    unsigned int a;
    asm("{ .reg .u64 t; cvta.to.shared.u64 t, %1; cvt.u32.u64 %0, t; }" : "=r"(a) : "l"(p));
    return a;
}
__device__ __forceinline__ unsigned int pkbf(__nv_bfloat16 a, __nv_bfloat16 b) {
    return (unsigned int)__bfloat16_as_ushort(a) |
           ((unsigned int)__bfloat16_as_ushort(b) << 16);
}

// ---------------- warp-mma + async helpers ----------------
__device__ __forceinline__ void ldmx4(unsigned int* r, unsigned int addr) {
    asm volatile("ldmatrix.sync.aligned.m8n8.x4.shared.b16 {%0,%1,%2,%3}, [%4];"
                 : "=r"(r[0]), "=r"(r[1]), "=r"(r[2]), "=r"(r[3]) : "r"(addr));
}
__device__ __forceinline__ void mma16816(float* c, const unsigned int* a,
                                         const unsigned int b0, const unsigned int b1) {
    asm volatile(
        "mma.sync.aligned.m16n8k16.row.col.f32.bf16.bf16.f32 "
        "{%0,%1,%2,%3}, {%4,%5,%6,%7}, {%8,%9}, {%0,%1,%2,%3};"
        : "+f"(c[0]), "+f"(c[1]), "+f"(c[2]), "+f"(c[3])
        : "r"(a[0]), "r"(a[1]), "r"(a[2]), "r"(a[3]), "r"(b0), "r"(b1));
}
__device__ __forceinline__ void bulk_cp(unsigned int dst, const void* src,
                                        unsigned int bytes, unsigned int mbar) {
    asm volatile(
        "cp.async.bulk.shared::cta.global.mbarrier::complete_tx::bytes [%0], [%1], %2, [%3];"
        :: "r"(dst), "l"(src), "r"(bytes), "r"(mbar) : "memory");
}
__device__ __forceinline__ void cpa16(unsigned int dst, const void* src) {
    asm volatile("cp.async.cg.shared.global [%0], [%1], 16;" :: "r"(dst), "l"(src) : "memory");
}
__device__ __forceinline__ void mbar_init(unsigned int mbar, unsigned int cnt) {
    asm volatile("mbarrier.init.shared.b64 [%0], %1;" :: "r"(mbar), "r"(cnt) : "memory");
}
__device__ __forceinline__ void mbar_expect(unsigned int mbar, unsigned int bytes) {
    asm volatile("mbarrier.arrive.expect_tx.shared.b64 _, [%0], %1;"
                 :: "r"(mbar), "r"(bytes) : "memory");
}
__device__ __forceinline__ void mbar_wait(unsigned int mbar, unsigned int parity) {
    asm volatile(
        "{\n\t"
        ".reg .pred P1;\n\t"
        "LAB_WAIT_%=:\n\t"
        "mbarrier.try_wait.parity.acquire.cta.shared::cta.b64 P1, [%0], %1, 0x989680;\n\t"
        "@P1 bra.uni DONE_%=;\n\t"
        "bra.uni LAB_WAIT_%=;\n\t"
        "DONE_%=:\n\t"
        "}"
        :: "r"(mbar), "r"(parity) : "memory");
}

// ---------------- LayerNorm (mode 0: head layout fp32; mode 1: bf16 splits) ----------------
__global__ void ln_kernel(const float* __restrict__ x, const float* __restrict__ g,
                          const float* __restrict__ be, float* __restrict__ out,
                          __nv_bfloat16* __restrict__ ohi, __nv_bfloat16* __restrict__ olo,
                          int mode) {
    __shared__ float sred[256];
    int row = blockIdx.x;
    int tid = threadIdx.x;
    const float* xr = x + (size_t)row * DD;
    float v[4];
    float s = 0.f;
#pragma unroll
    for (int kk = 0; kk < 4; kk++) { v[kk] = xr[tid + 256 * kk]; s += v[kk]; }
    s = blockReduceSum(s, sred);
    float mean = s * (1.0f / DD);
    float qv = 0.f;
#pragma unroll
    for (int kk = 0; kk < 4; kk++) { float d = v[kk] - mean; qv += d * d; }
    qv = blockReduceSum(qv, sred);
    float inv = rsqrtf(qv * (1.0f / DD) + 1e-5f);
    int b = row / SS, sidx_ = row % SS;
#pragma unroll
    for (int kk = 0; kk < 4; kk++) {
        int j = tid + 256 * kk;
        float y = (v[kk] - mean) * inv * g[j] + be[j];
        if (mode == 0) {
            int h = j >> 6, d = j & 63;
            out[(((size_t)(b * HH + h)) * SS + sidx_) * HDIM + d] = y;
        } else {
            __nv_bfloat16 hi, lo; split_bf16(y, hi, lo);
            size_t ad = rswz(row, 128, j >> 3, j & 7);
            ohi[ad] = hi; olo[ad] = lo;
        }
    }
}

// ---------------- QKV projection: q/k -> swizzled bf16 splits; v -> state ----------------
__global__ void qkv_kernel(const float* __restrict__ xh, const float* __restrict__ Wq,
                           const float* __restrict__ Wk, const float* __restrict__ Wv,
                           __nv_bfloat16* __restrict__ qhi, __nv_bfloat16* __restrict__ qlo,
                           __nv_bfloat16* __restrict__ khi, __nv_bfloat16* __restrict__ klo,
                           float* __restrict__ stf, __nv_bfloat16* __restrict__ sthi,
                           __nv_bfloat16* __restrict__ stlo) {
    __shared__ float Xs[64][65];
    __shared__ float Ws[64][65];
    int s0 = blockIdx.x * 64;
    int bh = blockIdx.y;
    int h = bh % HH;
    int tid = threadIdx.x, tx = tid % 16, ty = tid / 16;
    const float* xb = xh + ((size_t)bh * SS + s0) * HDIM;
    for (int t = tid; t < 1024; t += 256) {
        int r = t / 16, c4 = t % 16;
        float4 vv = *(const float4*)(xb + r * 64 + c4 * 4);
        Xs[r][c4 * 4 + 0] = vv.x; Xs[r][c4 * 4 + 1] = vv.y;
        Xs[r][c4 * 4 + 2] = vv.z; Xs[r][c4 * 4 + 3] = vv.w;
    }
    const float* Wm[3] = { Wq + h * 4096, Wk + h * 4096, Wv + h * 4096 };
    for (int m = 0; m < 3; m++) {
        __syncthreads();
        for (int t = tid; t < 1024; t += 256) {
            int r = t / 16, c4 = t % 16;
            float4 vv = *(const float4*)(Wm[m] + r * 64 + c4 * 4);
            Ws[r][c4 * 4 + 0] = vv.x; Ws[r][c4 * 4 + 1] = vv.y;
            Ws[r][c4 * 4 + 2] = vv.z; Ws[r][c4 * 4 + 3] = vv.w;
        }
        __syncthreads();
        float acc[4][4] = {};
#pragma unroll 8
        for (int kk = 0; kk < 64; kk++) {
            float xv[4], wv[4];
#pragma unroll
            for (int i = 0; i < 4; i++) xv[i] = Xs[ty * 4 + i][kk];
#pragma unroll
            for (int j = 0; j < 4; j++) wv[j] = Ws[kk][tx * 4 + j];
#pragma unroll
            for (int i = 0; i < 4; i++)
#pragma unroll
                for (int j = 0; j < 4; j++) acc[i][j] += xv[i] * wv[j];
        }
#pragma unroll
        for (int i = 0; i < 4; i++) {
            int srow = s0 + ty * 4 + i;
#pragma unroll
            for (int j = 0; j < 4; j++) {
                int c = tx * 4 + j;
                float v = acc[i][j];
                __nv_bfloat16 hi, lo; split_bf16(v, hi, lo);
                if (m == 0) {
                    size_t ad = ((size_t)bh * 2048 + srow) * 64 +
                                ((((c >> 3) ^ srow) & 7) << 3) + (c & 7);
                    qhi[ad] = hi; qlo[ad] = lo;
                } else if (m == 1) {
                    size_t ad = ((size_t)bh * 2048 + srow) * 64 +
                                ((((c >> 3) ^ srow) & 7) << 3) + (c & 7);
                    khi[ad] = hi; klo[ad] = lo;
                } else {
                    size_t lb = ((size_t)bh << 18) + ((size_t)c << 11) + srow;
                    stf[lb] = v; stf[lb + 131072] = 0.f;
                    size_t th = sidx(bh, c, srow), tb = sidx(bh, c + 64, srow);
                    sthi[th] = hi; stlo[th] = lo;
                    sthi[tb] = __float2bfloat16(0.f);
                    stlo[tb] = __float2bfloat16(0.f);
                }
            }
        }
    }
}

// ---------------- weight transpose+split: W[K][N] fp32 -> WT hi/lo [N][K] swizzled ----------------
__global__ void wsplit_kernel(const float* __restrict__ W, __nv_bfloat16* __restrict__ Whi,
                              __nv_bfloat16* __restrict__ Wlo, int K, int N) {
    __shared__ float t[32][33];
    int k0 = blockIdx.x * 32, n0 = blockIdx.y * 32;
    int tx = threadIdx.x, ty = threadIdx.y;
    for (int i = ty; i < 32; i += 8)
        t[i][tx] = W[(size_t)(k0 + i) * N + n0 + tx];
    __syncthreads();
    if (ty < 4) {
        int nl = tx, u = ty;
        int row = n0 + nl;
        unsigned int hv[4], lv[4];
#pragma unroll
        for (int e2 = 0; e2 < 4; e2++) {
            __nv_bfloat16 h0, l0, h1, l1;
            split_bf16(t[u * 8 + 2 * e2][nl], h0, l0);
            split_bf16(t[u * 8 + 2 * e2 + 1][nl], h1, l1);
            hv[e2] = pkbf(h0, h1);
            lv[e2] = pkbf(l0, l1);
        }
        int ug = (k0 >> 3) + u;
        int up = (ug & ~7) | ((ug ^ row) & 7);
        size_t ad = ((size_t)row * (K >> 3) + up) * 8;
        *(uint4*)(Whi + ad) = make_uint4(hv[0], hv[1], hv[2], hv[3]);
        *(uint4*)(Wlo + ad) = make_uint4(lv[0], lv[1], lv[2], lv[3]);
    }
}

// ---------------- row softmax -> bf16 hi/lo in chunk-tiled layout ----------------
__global__ void softmax_kernel(const float* __restrict__ A,
                               __nv_bfloat16* __restrict__ Ahi,
                               __nv_bfloat16* __restrict__ Alo) {
    __shared__ float sred[256];
    size_t rb = (size_t)blockIdx.x * SS;
    const float* ar = A + rb;
    int bh = blockIdx.x >> 11, m = blockIdx.x & 2047;
    int tid = threadIdx.x;
    float r[8];
    float mx = -1e30f;
#pragma unroll
    for (int kk = 0; kk < 8; kk++) { r[kk] = ar[tid + 256 * kk]; mx = fmaxf(mx, r[kk]); }
    mx = blockReduceMax(mx, sred);
    float s = 0.f;
#pragma unroll
    for (int kk = 0; kk < 8; kk++) { r[kk] = __expf(r[kk] - mx); s += r[kk]; }
    s = blockReduceSum(s, sred);
    float inv = 1.0f / s;
#pragma unroll
    for (int kk = 0; kk < 8; kk++) {
        float val = r[kk] * inv;
        __nv_bfloat16 hi, lo; split_bf16(val, hi, lo);
        size_t ai = aidx(bh, m, tid + 256 * kk);
        Ahi[ai] = hi;
        Alo[ai] = lo;
    }
}

// ---------------- HMMA scores: S[bh][m][n] = 0.125 * q[m,:].k[n,:] ----------------
#define SMEM_SC (128 + 4 * 16384)
__global__ void __launch_bounds__(256) scores_mma(
    const __nv_bfloat16* __restrict__ qhi, const __nv_bfloat16* __restrict__ qlo,
    const __nv_bfloat16* __restrict__ khi, const __nv_bfloat16* __restrict__ klo,
    float* __restrict__ A)
{
    extern __shared__ char smem[];
    unsigned int sb = s2u(smem);
    int tid = threadIdx.x, wid = tid >> 5, lane = tid & 31;
    int m0 = blockIdx.x << 7, n0 = blockIdx.y << 7;
    int bh = blockIdx.z;
    int wm = (wid >> 2) * 64, wn = (wid & 3) * 32;

    if (tid == 0) mbar_init(sb, 1);
    __syncthreads();
    if (tid == 0) {
        mbar_expect(sb, 4 * 16384);
        size_t qoff = ((size_t)bh * 2048 + m0) * 128;
        size_t koff = ((size_t)bh * 2048 + n0) * 128;
        bulk_cp(sb + 128,          (const char*)qhi + qoff, 16384, sb);
        bulk_cp(sb + 128 + 16384,  (const char*)qlo + qoff, 16384, sb);
        bulk_cp(sb + 128 + 32768,  (const char*)khi + koff, 16384, sb);
        bulk_cp(sb + 128 + 49152,  (const char*)klo + koff, 16384, sb);
    }

    float c[4][4][4];
#pragma unroll
    for (int i = 0; i < 4; i++)
#pragma unroll
        for (int j = 0; j < 4; j++)
#pragma unroll
            for (int r = 0; r < 4; r++) c[i][j][r] = 0.f;

    int arow = ((lane >> 3) & 1) * 8 + (lane & 7);
    int brow = (lane >> 4) * 8 + (lane & 7);
    int ua = (lane >> 4);
    int ub = ((lane >> 3) & 1);
    int rx = lane & 7;
    unsigned int aRow = (wm + arow) * 128;
    unsigned int bRow = (wn + brow) * 128;

    mbar_wait(sb, 0);
    unsigned int base = sb + 128;
#pragma unroll
    for (int ks = 0; ks < 4; ks++) {
        unsigned int au = (unsigned int)(((ua + 2 * ks) ^ rx) << 4);
        unsigned int bu = (unsigned int)(((ub + 2 * ks) ^ rx) << 4);
        unsigned int a[4][4];
        unsigned int b[2][4];
#pragma unroll
        for (int ma = 0; ma < 4; ma++) ldmx4(a[ma], base + aRow + ma * 2048 + au);
#pragma unroll
        for (int p = 0; p < 2; p++) ldmx4(b[p], base + 32768 + bRow + p * 2048 + bu);
#pragma unroll
        for (int ma = 0; ma < 4; ma++)
#pragma unroll
            for (int na = 0; na < 4; na++)
                mma16816(c[ma][na], a[ma], b[na >> 1][(na & 1) * 2],
                         b[na >> 1][(na & 1) * 2 + 1]);
#pragma unroll
        for (int ma = 0; ma < 4; ma++)
            ldmx4(a[ma], base + 16384 + aRow + ma * 2048 + au);
#pragma unroll
        for (int ma = 0; ma < 4; ma++)
#pragma unroll
            for (int na = 0; na < 4; na++)
                mma16816(c[ma][na], a[ma], b[na >> 1][(na & 1) * 2],
                         b[na >> 1][(na & 1) * 2 + 1]);
#pragma unroll
        for (int ma = 0; ma < 4; ma++) ldmx4(a[ma], base + aRow + ma * 2048 + au);
#pragma unroll
        for (int p = 0; p < 2; p++)
            ldmx4(b[p], base + 49152 + bRow + p * 2048 + bu);
#pragma unroll
        for (int ma = 0; ma < 4; ma++)
#pragma unroll
            for (int na = 0; na < 4; na++)
                mma16816(c[ma][na], a[ma], b[na >> 1][(na & 1) * 2],
                         b[na >> 1][(na & 1) * 2 + 1]);
    }

    int g = lane >> 2, tg = lane & 3;
    float* Ab = A + ((size_t)bh << 22);
#pragma unroll
    for (int ma = 0; ma < 4; ma++) {
        int m_ = m0 + wm + ma * 16 + g;
#pragma unroll
        for (int na = 0; na < 4; na++) {
            int n_ = n0 + wn + na * 8 + 2 * tg;
            *(float2*)(Ab + (size_t)m_ * 2048 + n_) =
                make_float2(c[ma][na][0] * 0.125f, c[ma][na][1] * 0.125f);
            *(float2*)(Ab + (size_t)(m_ + 8) * 2048 + n_) =
                make_float2(c[ma][na][2] * 0.125f, c[ma][na][3] * 0.125f);
        }
    }
}

// ---------------- HMMA A-apply, cp.async.bulk 2-stage pipeline (round-12 proven) ----------------
#define STAGE_B 65536
#define SMEM_BULK (128 + 2 * STAGE_B)
__global__ void __launch_bounds__(256) apply_mma(
    const __nv_bfloat16* __restrict__ Ahi, const __nv_bfloat16* __restrict__ Alo,
    const __nv_bfloat16* __restrict__ Bhi, const __nv_bfloat16* __restrict__ Blo,
    float* __restrict__ Zt)
{
    extern __shared__ char smem[];
    unsigned int sb = s2u(smem);
    int tid = threadIdx.x, wid = tid >> 5, lane = tid & 31;
    int m0 = blockIdx.x << 7;
    int bh = blockIdx.y;
    int wm = (wid >> 2) * 64, wn = (wid & 3) * 32;

    unsigned int mb[2] = { sb, sb + 8 };
    if (tid == 0) { mbar_init(mb[0], 1); mbar_init(mb[1], 1); }
    __syncthreads();

    const char* pAh = (const char*)Ahi;
    const char* pAl = (const char*)Alo;
    const char* pBh = (const char*)Bhi;
    const char* pBl = (const char*)Blo;

    float c[4][4][4];
#pragma unroll
    for (int i = 0; i < 4; i++)
#pragma unroll
        for (int j = 0; j < 4; j++)
#pragma unroll
            for (int r = 0; r < 4; r++) c[i][j][r] = 0.f;

    int arow = ((lane >> 3) & 1) * 8 + (lane & 7);
    int brow = (lane >> 4) * 8 + (lane & 7);
    int ua = (lane >> 4);
    int ub = ((lane >> 3) & 1);
    int rx = lane & 7;
    unsigned int aRow = (wm + arow) * 128;
    unsigned int bRow = (wn + brow) * 128;

    if (tid == 0) {
        mbar_expect(mb[0], 4 * 16384);
        unsigned int dst = sb + 128;
        size_t aoff = (((size_t)bh * 32 + 0) * 2048 + m0) * 128;
        size_t boff = (((size_t)bh * 32 + 0) * 128) * 128;
        bulk_cp(dst,          pAh + aoff, 16384, mb[0]);
        bulk_cp(dst + 16384,  pAl + aoff, 16384, mb[0]);
        bulk_cp(dst + 32768,  pBh + boff, 16384, mb[0]);
        bulk_cp(dst + 49152,  pBl + boff, 16384, mb[0]);
    }

    for (int ck = 0; ck < 32; ck++) {
        int s = ck & 1;
        if (tid == 0 && ck + 1 < 32) {
            int s2 = (ck + 1) & 1;
            mbar_expect(mb[s2], 4 * 16384);
            unsigned int dst = sb + 128 + s2 * STAGE_B;
            size_t aoff = (((size_t)bh * 32 + (ck + 1)) * 2048 + m0) * 128;
            size_t boff = (((size_t)bh * 32 + (ck + 1)) * 128) * 128;
            bulk_cp(dst,          pAh + aoff, 16384, mb[s2]);
            bulk_cp(dst + 16384,  pAl + aoff, 16384, mb[s2]);
            bulk_cp(dst + 32768,  pBh + boff, 16384, mb[s2]);
            bulk_cp(dst + 49152,  pBl + boff, 16384, mb[s2]);
        }
        mbar_wait(mb[s], (ck >> 1) & 1);

        unsigned int base = sb + 128 + s * STAGE_B;
#pragma unroll
        for (int ks = 0; ks < 4; ks++) {
            unsigned int au = (unsigned int)(((ua + 2 * ks) ^ rx) << 4);
            unsigned int bu = (unsigned int)(((ub + 2 * ks) ^ rx) << 4);
            unsigned int a[4][4];
            unsigned int b[2][4];
#pragma unroll
            for (int ma = 0; ma < 4; ma++) ldmx4(a[ma], base + aRow + ma * 2048 + au);
#pragma unroll
            for (int p = 0; p < 2; p++) ldmx4(b[p], base + 32768 + bRow + p * 2048 + bu);
#pragma unroll
            for (int ma = 0; ma < 4; ma++)
#pragma unroll
                for (int na = 0; na < 4; na++)
                    mma16816(c[ma][na], a[ma], b[na >> 1][(na & 1) * 2],
                             b[na >> 1][(na & 1) * 2 + 1]);
#pragma unroll
            for (int ma = 0; ma < 4; ma++)
                ldmx4(a[ma], base + 16384 + aRow + ma * 2048 + au);
#pragma unroll
            for (int ma = 0; ma < 4; ma++)
#pragma unroll
                for (int na = 0; na < 4; na++)
                    mma16816(c[ma][na], a[ma], b[na >> 1][(na & 1) * 2],
                             b[na >> 1][(na & 1) * 2 + 1]);
#pragma unroll
            for (int ma = 0; ma < 4; ma++) ldmx4(a[ma], base + aRow + ma * 2048 + au);
#pragma unroll
            for (int p = 0; p < 2; p++)
                ldmx4(b[p], base + 49152 + bRow + p * 2048 + bu);
#pragma unroll
            for (int ma = 0; ma < 4; ma++)
#pragma unroll
                for (int na = 0; na < 4; na++)
                    mma16816(c[ma][na], a[ma], b[na >> 1][(na & 1) * 2],
                             b[na >> 1][(na & 1) * 2 + 1]);
        }
        __syncthreads();
    }

    int g = lane >> 2, tg = lane & 3;
    size_t zb = (((size_t)bh) << 18) + m0;
#pragma unroll
    for (int ma = 0; ma < 4; ma++) {
        int mloc = wm + ma * 16 + g;
#pragma unroll
        for (int na = 0; na < 4; na++) {
            int nloc = wn + na * 8 + tg * 2;
            float* p = Zt + zb + ((size_t)nloc << 11) + mloc;
            p[0]          = c[ma][na][0];
            p[2048]       = c[ma][na][1];
            p[8]          = c[ma][na][2];
            p[2048 + 8]   = c[ma][na][3];
        }
    }
}

// ---------------- HMMA MLP GEMM, cp.async 2-stage; epi 1: gelu+bias->splits; 2: bias+resid->fp32
#define SMEM_MLP (2 * 65536)
__global__ void __launch_bounds__(256) mlp_mma(
    const __nv_bfloat16* __restrict__ Ah, const __nv_bfloat16* __restrict__ Al,
    const __nv_bfloat16* __restrict__ Bh, const __nv_bfloat16* __restrict__ Bl,
    float* __restrict__ out, __nv_bfloat16* __restrict__ ohi, __nv_bfloat16* __restrict__ olo,
    const float* __restrict__ bias, const float* __restrict__ resid,
    int K, int ldc, int epi)
{
    extern __shared__ char smem[];
    unsigned int sb = s2u(smem);
    int tid = threadIdx.x, wid = tid >> 5, lane = tid & 31;
    int m0 = blockIdx.x << 7, n0 = blockIdx.y << 7;
    int wm = (wid >> 2) * 64, wn = (wid & 3) * 32;
    int NC = K >> 6;

    float c[4][4][4];
#pragma unroll
    for (int i = 0; i < 4; i++)
#pragma unroll
        for (int j = 0; j < 4; j++)
#pragma unroll
            for (int r = 0; r < 4; r++) c[i][j][r] = 0.f;

    int arow = ((lane >> 3) & 1) * 8 + (lane & 7);
    int brow = (lane >> 4) * 8 + (lane & 7);
    int ua = (lane >> 4);
    int ub = ((lane >> 3) & 1);
    int rx = lane & 7;
    unsigned int aRow = (wm + arow) * 128;
    unsigned int bRow = (wn + brow) * 128;

    const char* srcs[4] = { (const char*)Ah, (const char*)Al,
                            (const char*)Bh, (const char*)Bl };

    // prologue: chunk 0 -> stage 0
#pragma unroll
    for (int i = 0; i < 16; i++) {
        int idx = tid + (i << 8);
        int tile = idx >> 10, r = (idx >> 3) & 127, u = idx & 7;
        int row = (tile < 2 ? m0 : n0) + r;
        cpa16(sb + (tile << 14) + (r << 7) + (u << 4),
              srcs[tile] + ((size_t)row * K) * 2 + (u << 4));
    }
    asm volatile("cp.async.commit_group;" ::: "memory");

    for (int ck = 0; ck < NC; ck++) {
        if (ck + 1 < NC) {
            int s2 = (ck + 1) & 1;
#pragma unroll
            for (int i = 0; i < 16; i++) {
                int idx = tid + (i << 8);
                int tile = idx >> 10, r = (idx >> 3) & 127, u = idx & 7;
                int row = (tile < 2 ? m0 : n0) + r;
                cpa16(sb + s2 * 65536 + (tile << 14) + (r << 7) + (u << 4),
                      srcs[tile] + ((size_t)row * K + ((ck + 1) << 6)) * 2 + (u << 4));
            }
            asm volatile("cp.async.commit_group;" ::: "memory");
            asm volatile("cp.async.wait_group 1;" ::: "memory");
        } else {
            asm volatile("cp.async.wait_group 0;" ::: "memory");
        }
        __syncthreads();

        unsigned int base = sb + (ck & 1) * 65536;
#pragma unroll
        for (int ks = 0; ks < 4; ks++) {
            unsigned int au = (unsigned int)(((ua + 2 * ks) ^ rx) << 4);
            unsigned int bu = (unsigned int)(((ub + 2 * ks) ^ rx) << 4);
            unsigned int a[4][4];
            unsigned int b[2][4];
#pragma unroll
            for (int ma = 0; ma < 4; ma++) ldmx4(a[ma], base + aRow + ma * 2048 + au);
#pragma unroll
            for (int p = 0; p < 2; p++) ldmx4(b[p], base + 32768 + bRow + p * 2048 + bu);
#pragma unroll
            for (int ma = 0; ma < 4; ma++)
#pragma unroll
                for (int na = 0; na < 4; na++)
                    mma16816(c[ma][na], a[ma], b[na >> 1][(na & 1) * 2],
                             b[na >> 1][(na & 1) * 2 + 1]);
#pragma unroll
            for (int ma = 0; ma < 4; ma++)
                ldmx4(a[ma], base + 16384 + aRow + ma * 2048 + au);
#pragma unroll
            for (int ma = 0; ma < 4; ma++)
#pragma unroll
                for (int na = 0; na < 4; na++)
                    mma16816(c[ma][na], a[ma], b[na >> 1][(na & 1) * 2],
                             b[na >> 1][(na & 1) * 2 + 1]);
#pragma unroll
            for (int ma = 0; ma < 4; ma++) ldmx4(a[ma], base + aRow + ma * 2048 + au);
#pragma unroll
            for (int p = 0; p < 2; p++)
                ldmx4(b[p], base + 49152 + bRow + p * 2048 + bu);
#pragma unroll
            for (int ma = 0; ma < 4; ma++)
#pragma unroll
                for (int na = 0; na < 4; na++)
                    mma16816(c[ma][na], a[ma], b[na >> 1][(na & 1) * 2],
                             b[na >> 1][(na & 1) * 2 + 1]);
        }
        __syncthreads();
    }

    int g = lane >> 2, tg = lane & 3;
#pragma unroll
    for (int ma = 0; ma < 4; ma++) {
#pragma unroll
        for (int na = 0; na < 4; na++) {
            int n_ = n0 + wn + na * 8 + 2 * tg;
            float b0 = bias[n_], b1 = bias[n_ + 1];
#pragma unroll
            for (int half = 0; half < 2; half++) {
                int m_ = m0 + wm + ma * 16 + g + half * 8;
                float v0 = c[ma][na][half * 2 + 0] + b0;
                float v1 = c[ma][na][half * 2 + 1] + b1;
                if (epi == 1) {
                    v0 = gelu_tanh(v0); v1 = gelu_tanh(v1);
                    __nv_bfloat16 h0, l0, h1, l1;
                    split_bf16(v0, h0, l0); split_bf16(v1, h1, l1);
                    size_t ad = rswz(m_, ldc >> 3, n_ >> 3, n_ & 7);
                    *(unsigned int*)(ohi + ad) = pkbf(h0, h1);
                    *(unsigned int*)(olo + ad) = pkbf(l0, l1);
                } else {
                    float2 rv = *(const float2*)(resid + (size_t)m_ * ldc + n_);
                    *(float2*)(out + (size_t)m_ * ldc + n_) =
                        make_float2(v0 + rv.x, v1 + rv.y);
                }
            }
        }
    }
}

// ---------------- ODE elementwise ----------------
#define CA 0.99500416527802576610f
#define SA 0.09983341664682815230f

__global__ void eval1_kernel(const float* __restrict__ st, const float* __restrict__ z,
                             const float* __restrict__ omega, float* __restrict__ d1,
                             float* __restrict__ apf, __nv_bfloat16* __restrict__ aphi,
                             __nv_bfloat16* __restrict__ aplo,
                             float* __restrict__ attnv, int first) {
    int i = blockIdx.x * 256 + threadIdx.x;
    int bh = i >> 17;
    int w = i & 131071;
    int d = w >> 11;
    int k = w & 2047;
    size_t base = ((size_t)bh << 18) + ((size_t)d << 11) + k;
    size_t bb = base + 131072;
    float a = st[base], b = st[bb];
    float za = z[base], zb = z[bb];
    float om = omega[((bh & (HH - 1)) << 6) + d];
    float r2 = a * a + b * b;
    float ra = za * CA + zb * SA;
    float rb = zb * CA - za * SA;
    float da = (1.0f - r2) * a - om * b + 3.0f * (ra - a);
    float db = (1.0f - r2) * b + om * a + 3.0f * (rb - b);
    d1[base] = da; d1[bb] = db;
    float apv = a + 0.02f * da, bpv = b + 0.02f * db;
    apf[base] = apv; apf[bb] = bpv;
    __nv_bfloat16 hi, lo;
    size_t th = sidx(bh, d, k), tb = sidx(bh, d + 64, k);
    split_bf16(apv, hi, lo); aphi[th] = hi; aplo[th] = lo;
    split_bf16(bpv, hi, lo); aphi[tb] = hi; aplo[tb] = lo;
    if (first) attnv[i] = za;
}

__global__ void eval2_kernel(float* __restrict__ st, const float* __restrict__ apf,
                             const float* __restrict__ z, const float* __restrict__ d1,
                             const float* __restrict__ omega,
                             __nv_bfloat16* __restrict__ sthi, __nv_bfloat16* __restrict__ stlo) {
    int i = blockIdx.x * 256 + threadIdx.x;
    int bh = i >> 17;
    int w = i & 131071;
    int d = w >> 11;
    int k = w & 2047;
    size_t base = ((size_t)bh << 18) + ((size_t)d << 11) + k;
    size_t bb = base + 131072;
    float a = st[base], b = st[bb];
    float ap = apf[base], bp = apf[bb];
    float zap = z[base], zbp = z[bb];
    float da1 = d1[base], db1 = d1[bb];
    float om = omega[((bh & (HH - 1)) << 6) + d];
    float r2 = ap * ap + bp * bp;
    float ra = zap * CA + zbp * SA;
    float rb = zbp * CA - zap * SA;
    float da2 = (1.0f - r2) * ap - om * bp + 3.0f * (ra - ap);
    float db2 = (1.0f - r2) * bp + om * ap + 3.0f * (rb - bp);
    float na = a + 0.01f * (da1 + da2);
    float nb = b + 0.01f * (db1 + db2);
    st[base] = na; st[bb] = nb;
    __nv_bfloat16 hi, lo;
    size_t th = sidx(bh, d, k), tb = sidx(bh, d + 64, k);
    split_bf16(na, hi, lo); sthi[th] = hi; stlo[th] = lo;
    split_bf16(nb, hi, lo); sthi[tb] = hi; stlo[tb] = lo;
}

__global__ void mixed_kernel(const float* __restrict__ st, const float* __restrict__ attnv,
                             float* __restrict__ mixed) {
    int i = blockIdx.x * 256 + threadIdx.x;
    int bh = i >> 17;
    int w = i & 131071;
    size_t base = ((size_t)bh << 18) + w;
    mixed[i] = 0.3f * attnv[i] + 0.7f * st[base];
}

// ---------------- output projection + residual ----------------
__global__ void proj_kernel(const float* __restrict__ mixed, const float* __restrict__ Wo,
                            const float* __restrict__ x, float* __restrict__ x1) {
    __shared__ float Xs[64][65];
    __shared__ float Ws[64][65];
    int s0 = blockIdx.x * 64;
    int bh = blockIdx.y;
    int h = bh % HH, b = bh / HH;
    int tid = threadIdx.x, tx = tid % 16, ty = tid / 16;
    const float* xb = mixed + (((size_t)bh) << 17) + s0;
    const float* Wb = Wo + h * 4096;
    for (int t = tid; t < 1024; t += 256) {
        int d = t >> 4, c4 = t & 15;
        float4 vv = *(const float4*)(xb + (size_t)d * 2048 + c4 * 4);
        Xs[c4 * 4 + 0][d] = vv.x; Xs[c4 * 4 + 1][d] = vv.y;
        Xs[c4 * 4 + 2][d] = vv.z; Xs[c4 * 4 + 3][d] = vv.w;
        float4 wv = *(const float4*)(Wb + (t / 16) * 64 + (t % 16) * 4);
        Ws[t / 16][(t % 16) * 4 + 0] = wv.x; Ws[t / 16][(t % 16) * 4 + 1] = wv.y;
        Ws[t / 16][(t % 16) * 4 + 2] = wv.z; Ws[t / 16][(t % 16) * 4 + 3] = wv.w;
    }
    __syncthreads();
    float acc[4][4] = {};
#pragma unroll 8
    for (int kk = 0; kk < 64; kk++) {
        float xv[4], wv[4];
#pragma unroll
        for (int i = 0; i < 4; i++) xv[i] = Xs[ty * 4 + i][kk];
#pragma unroll
        for (int j = 0; j < 4; j++) wv[j] = Ws[kk][tx * 4 + j];
#pragma unroll
        for (int i = 0; i < 4; i++)
#pragma unroll
            for (int j = 0; j < 4; j++) acc[i][j] += xv[i] * wv[j];
    }
#pragma unroll
    for (int i = 0; i < 4; i++) {
        int srow = s0 + ty * 4 + i;
#pragma unroll
        for (int j = 0; j < 4; j++) {
            int c = tx * 4 + j;
            size_t o = ((size_t)b * SS + srow) * DD + h * 64 + c;
            x1[o] = x[o] + acc[i][j];
        }
    }
}

// ---------------- launch ----------------
extern "C" void kernel_launch(void* const* d_in, const int* in_sizes, int n_in,
                              void* d_out, int out_size) {
    const float* x     = (const float*)d_in[0];
    const float* Wq    = (const float*)d_in[1];
    const float* Wk    = (const float*)d_in[2];
    const float* Wv    = (const float*)d_in[3];
    const float* Wo    = (const float*)d_in[4];
    const float* omega = (const float*)d_in[5];
    const float* g1    = (const float*)d_in[6];
    const float* be1   = (const float*)d_in[7];
    const float* g2    = (const float*)d_in[8];
    const float* be2   = (const float*)d_in[9];
    const float* W1    = (const float*)d_in[10];
    const float* bf1   = (const float*)d_in[11];
    const float* W2    = (const float*)d_in[12];
    const float* bf2   = (const float*)d_in[13];
    float* out = (float*)d_out;

    float *xh, *A, *st, *apf, *z, *d1, *attnv, *mixed, *x1;
    __nv_bfloat16 *Ahi, *Alo, *qhi, *qlo, *khi, *klo, *sthi, *stlo, *aphi, *aplo;
    __nv_bfloat16 *xn2hi, *xn2lo, *w1thi, *w1tlo, *w2thi, *w2tlo, *hbhi, *hblo;
    cudaGetSymbolAddress((void**)&xh,    g_xh);
    cudaGetSymbolAddress((void**)&A,     g_A);
    cudaGetSymbolAddress((void**)&Ahi,   g_Ahi);
    cudaGetSymbolAddress((void**)&Alo,   g_Alo);
    cudaGetSymbolAddress((void**)&qhi,   g_qhi);
    cudaGetSymbolAddress((void**)&qlo,   g_qlo);
    cudaGetSymbolAddress((void**)&khi,   g_khi);
    cudaGetSymbolAddress((void**)&klo,   g_klo);
    cudaGetSymbolAddress((void**)&st,    g_st);
    cudaGetSymbolAddress((void**)&sthi,  g_sthi);
    cudaGetSymbolAddress((void**)&stlo,  g_stlo);
    cudaGetSymbolAddress((void**)&apf,   g_apf);
    cudaGetSymbolAddress((void**)&aphi,  g_aphi);
    cudaGetSymbolAddress((void**)&aplo,  g_aplo);
    cudaGetSymbolAddress((void**)&z,     g_z);
    cudaGetSymbolAddress((void**)&d1,    g_d1);
    cudaGetSymbolAddress((void**)&attnv, g_attnv);
    cudaGetSymbolAddress((void**)&mixed, g_mixed);
    cudaGetSymbolAddress((void**)&x1,    g_x1);
    cudaGetSymbolAddress((void**)&xn2hi, g_xn2hi);
    cudaGetSymbolAddress((void**)&xn2lo, g_xn2lo);
    cudaGetSymbolAddress((void**)&w1thi, g_w1thi);
    cudaGetSymbolAddress((void**)&w1tlo, g_w1tlo);
    cudaGetSymbolAddress((void**)&w2thi, g_w2thi);
    cudaGetSymbolAddress((void**)&w2tlo, g_w2tlo);
    cudaGetSymbolAddress((void**)&hbhi,  g_hbhi);
    cudaGetSymbolAddress((void**)&hblo,  g_hblo);

    cudaFuncSetAttribute(apply_mma,  cudaFuncAttributeMaxDynamicSharedMemorySize, SMEM_BULK);
    cudaFuncSetAttribute(scores_mma, cudaFuncAttributeMaxDynamicSharedMemorySize, SMEM_SC);
    cudaFuncSetAttribute(mlp_mma,    cudaFuncAttributeMaxDynamicSharedMemorySize, SMEM_MLP);

    // 0) weight transpose+split (independent)
    wsplit_kernel<<<dim3(DD / 32, DFFN / 32), dim3(32, 8)>>>(W1, w1thi, w1tlo, DD, DFFN);
    wsplit_kernel<<<dim3(DFFN / 32, DD / 32), dim3(32, 8)>>>(W2, w2thi, w2tlo, DFFN, DD);
    // 1) LN1 -> head layout
    ln_kernel<<<BB * SS, 256>>>(x, g1, be1, xh, nullptr, nullptr, 0);
    // 2) QKV (q/k -> swizzled splits; v -> state)
    qkv_kernel<<<dim3(SS / 64, BH), 256>>>(xh, Wq, Wk, Wv, qhi, qlo, khi, klo,
                                           st, sthi, stlo);
    // 3) scores on HMMA
    scores_mma<<<dim3(SS / 128, SS / 128, BH), 256, SMEM_SC>>>(qhi, qlo, khi, klo, A);
    // 4) softmax -> tiled bf16 hi/lo
    softmax_kernel<<<BH * SS, 256>>>(A, Ahi, Alo);
    // 5) 5 Heun steps
    for (int stp = 0; stp < 5; stp++) {
        apply_mma<<<dim3(SS / 128, BH), 256, SMEM_BULK>>>(Ahi, Alo, sthi, stlo, z);
        eval1_kernel<<<16384, 256>>>(st, z, omega, d1, apf, aphi, aplo, attnv,
                                     stp == 0 ? 1 : 0);
        apply_mma<<<dim3(SS / 128, BH), 256, SMEM_BULK>>>(Ahi, Alo, aphi, aplo, z);
        eval2_kernel<<<16384, 256>>>(st, apf, z, d1, omega, sthi, stlo);
    }
    // 6) mix
    mixed_kernel<<<16384, 256>>>(st, attnv, mixed);
    // 7) output projection + residual
    proj_kernel<<<dim3(SS / 64, BH), 256>>>(mixed, Wo, x, x1);
    // 8) LN2 -> bf16 splits
    ln_kernel<<<BB * SS, 256>>>(x1, g2, be2, nullptr, xn2hi, xn2lo, 1);
    // 9) MLP on HMMA
    mlp_mma<<<dim3(BB * SS / 128, DFFN / 128), 256, SMEM_MLP>>>(
        xn2hi, xn2lo, w1thi, w1tlo, nullptr, hbhi, hblo, bf1, nullptr, DD, DFFN, 1);
    mlp_mma<<<dim3(BB * SS / 128, DD / 128), 256, SMEM_MLP>>>(
        hbhi, hblo, w2thi, w2tlo, out, nullptr, nullptr, bf2, x1, DFFN, DD, 2);
}